// round 12
// baseline (speedup 1.0000x reference)
#include <cuda_runtime.h>
#include <cuda_fp16.h>
#include <math.h>
#include <cstdint>

#define H_   16
#define T_   2048
#define DIM_ 2048
#define DK_  64
#define E2_  128
#define LAMBDA_INIT_ 0.6192834728526787f
#define OUT_SCALE_   0.3807165271473213f
#define EPS_ 1e-5f

// ---------------- scratch ----------------------------------------------------
__device__ float g_att1[H_*T_*E2_];
__device__ float g_att2[H_*T_*E2_];
__device__ float g_lam[H_];
__device__ __align__(256) __half g_xhi[T_*DIM_];
__device__ __align__(256) __half g_wthi[3*H_*E2_*DIM_];   // [sel][h][e][d]
__device__ __align__(256) __half g_wtlo[3*H_*E2_*DIM_];
__device__ __align__(256) __half g_qh[H_*T_*E2_];
__device__ __align__(256) __half g_ql[H_*T_*E2_];
__device__ __align__(256) __half g_kh[H_*T_*E2_];
__device__ __align__(256) __half g_kl[H_*T_*E2_];
__device__ __align__(256) __half g_vh[H_*T_*E2_];
__device__ __align__(256) __half g_vl[H_*T_*E2_];

// ---------------- helpers ----------------------------------------------------
__device__ __forceinline__ uint32_t smem_to_u32(const void* p) {
    uint32_t a;
    asm("{ .reg .u64 t; cvta.to.shared.u64 t, %1; cvt.u32.u64 %0, t; }" : "=r"(a) : "l"(p));
    return a;
}
#define LDSM4(r, addr) \
    asm volatile("ldmatrix.sync.aligned.m8n8.x4.shared.b16 {%0,%1,%2,%3}, [%4];" \
        : "=r"((r)[0]), "=r"((r)[1]), "=r"((r)[2]), "=r"((r)[3]) : "r"(addr))
#define LDSMT4(r, addr) \
    asm volatile("ldmatrix.sync.aligned.m8n8.x4.trans.shared.b16 {%0,%1,%2,%3}, [%4];" \
        : "=r"((r)[0]), "=r"((r)[1]), "=r"((r)[2]), "=r"((r)[3]) : "r"(addr))
#define MMA16816(c, a, b) \
    asm volatile("mma.sync.aligned.m16n8k16.row.col.f32.f16.f16.f32 " \
        "{%0,%1,%2,%3}, {%4,%5,%6,%7}, {%8,%9}, {%0,%1,%2,%3};" \
        : "+f"((c)[0]), "+f"((c)[1]), "+f"((c)[2]), "+f"((c)[3]) \
        : "r"((a)[0]), "r"((a)[1]), "r"((a)[2]), "r"((a)[3]), "r"((b)[0]), "r"((b)[1]))
#define CP_ASYNC16(sa, ga) \
    asm volatile("cp.async.cg.shared.global [%0], [%1], 16;" :: "r"(sa), "l"(ga))
#define CP_COMMIT() asm volatile("cp.async.commit_group;" ::: "memory")

__device__ __forceinline__ uint32_t packh2(__half a, __half b) {
    __half2 h = __halves2half2(a, b);
    return *(uint32_t*)&h;
}

// ---------------- lambda -----------------------------------------------------
__global__ void lam_kernel(const float* __restrict__ lq1, const float* __restrict__ lq2,
                           const float* __restrict__ lk1, const float* __restrict__ lk2) {
    int h = threadIdx.x;
    if (h < H_) {
        float d1 = 0.f, d2 = 0.f;
        for (int d = 0; d < DK_; d++) {
            d1 += lq1[h*DK_ + d] * lk1[h*DK_ + d];
            d2 += lq2[h*DK_ + d] * lk2[h*DK_ + d];
        }
        g_lam[h] = expf(d1) - expf(d2) + LAMBDA_INIT_;
    }
}

// ---------------- prep: X to fp16 (hi only) ----------------------------------
__global__ void __launch_bounds__(256) split_x(const float* __restrict__ X) {
    int t = blockIdx.x;
    const float* xp = X + (size_t)t * DIM_;
    __half* hp = g_xhi + (size_t)t * DIM_;
    for (int j = threadIdx.x; j < DIM_; j += 256)
        hp[j] = __float2half_rn(xp[j]);
}

// ---------------- prep: transpose + split W ----------------------------------
__global__ void __launch_bounds__(256) transp_w(const float* __restrict__ Wq,
                                                const float* __restrict__ Wk,
                                                const float* __restrict__ Wv) {
    __shared__ float tile[32][33];
    int hs = blockIdx.z;
    int sel = hs >> 4, h = hs & 15;
    const float* W = sel == 0 ? Wq : (sel == 1 ? Wk : Wv);
    int d0 = blockIdx.x * 32;
    int e0 = blockIdx.y * 32;
    int tx = threadIdx.x & 31, ty = threadIdx.x >> 5;
    #pragma unroll
    for (int i = 0; i < 4; i++) {
        int d = d0 + ty + i * 8;
        tile[ty + i * 8][tx] = W[((size_t)h * DIM_ + d) * E2_ + e0 + tx];
    }
    __syncthreads();
    #pragma unroll
    for (int i = 0; i < 4; i++) {
        int e = e0 + ty + i * 8;
        float v = tile[tx][ty + i * 8];
        __half hi = __float2half_rn(v);
        size_t idx = ((size_t)hs * E2_ + e) * DIM_ + d0 + tx;
        g_wthi[idx] = hi;
        g_wtlo[idx] = __float2half_rn(v - __half2float(hi));
    }
}

// ---------------- projection via mma.sync: Xhi*(Whi+Wlo) (round-9 config) ----
#define PRJ_ROWB   144
#define PRJ_TILEB  (128*PRJ_ROWB)        // 18432
#define PRJ_STAGEB (3*PRJ_TILEB)         // 55296
#define PRJ_NSTG   32                    // 2048 / 64

__global__ void __launch_bounds__(256, 2) proj_mma() {
    extern __shared__ char smc[];
    uint32_t sbase = smem_to_u32(smc);
    int tid = threadIdx.x, lane = tid & 31, wid = tid >> 5;
    int tblk = blockIdx.x, h = blockIdx.y, sel = blockIdx.z;
    int row0 = tblk * 128;

    const char* gA0 = (const char*)g_xhi + (size_t)row0 * (DIM_ * 2);
    size_t wofs = (size_t)(sel * H_ + h) * E2_ * (DIM_ * 2);
    const char* gA1 = (const char*)g_wthi + wofs;
    const char* gA2 = (const char*)g_wtlo + wofs;

    int m0 = (wid >> 1) * 32, n0 = (wid & 1) * 64;
    float acc[2][8][4] = {};

    auto issue = [&](int s, int b) {
        uint32_t sb = sbase + b * PRJ_STAGEB;
        size_t k0b = (size_t)s * 128;
        #pragma unroll
        for (int i = 0; i < 4; i++) {
            int l = tid + i * 256;
            int row = l >> 3, seg = l & 7;
            size_t gofs = (size_t)row * (DIM_ * 2) + k0b + seg * 16;
            uint32_t sofs = row * PRJ_ROWB + seg * 16;
            CP_ASYNC16(sb + 0 * PRJ_TILEB + sofs, gA0 + gofs);
            CP_ASYNC16(sb + 1 * PRJ_TILEB + sofs, gA1 + gofs);
            CP_ASYNC16(sb + 2 * PRJ_TILEB + sofs, gA2 + gofs);
        }
        CP_COMMIT();
    };

    issue(0, 0);
    for (int s = 0; s < PRJ_NSTG; s++) {
        int b = s & 1;
        if (s < PRJ_NSTG - 1) issue(s + 1, b ^ 1);
        if (s < PRJ_NSTG - 1) asm volatile("cp.async.wait_group 1;" ::: "memory");
        else                  asm volatile("cp.async.wait_group 0;" ::: "memory");
        __syncthreads();

        uint32_t sA  = sbase + b * PRJ_STAGEB;
        uint32_t sBh = sA + PRJ_TILEB;
        uint32_t sBl = sBh + PRJ_TILEB;
        #pragma unroll
        for (int kk = 0; kk < 64; kk += 16) {
            uint32_t ah[2][4];
            #pragma unroll
            for (int mt = 0; mt < 2; mt++) {
                uint32_t off = (uint32_t)(m0 + mt * 16 + (lane & 15)) * PRJ_ROWB
                             + (kk + (lane >> 4) * 8) * 2;
                LDSM4(ah[mt], sA + off);
            }
            uint32_t bh[4][4], bl[4][4];
            #pragma unroll
            for (int np = 0; np < 4; np++) {
                uint32_t off = (uint32_t)(n0 + np * 16 + (lane & 7) + ((lane >> 4) & 1) * 8) * PRJ_ROWB
                             + (kk + ((lane >> 3) & 1) * 8) * 2;
                LDSM4(bh[np], sBh + off);
                LDSM4(bl[np], sBl + off);
            }
            #pragma unroll
            for (int mt = 0; mt < 2; mt++)
                #pragma unroll
                for (int nt = 0; nt < 8; nt++) {
                    uint32_t* bhp = &bh[nt >> 1][(nt & 1) * 2];
                    uint32_t* blp = &bl[nt >> 1][(nt & 1) * 2];
                    MMA16816(acc[mt][nt], ah[mt], bhp);
                    MMA16816(acc[mt][nt], ah[mt], blp);
                }
        }
        __syncthreads();
    }

    __half* Gh = (sel == 0 ? g_qh : (sel == 1 ? g_kh : g_vh)) + (size_t)h * T_ * E2_;
    __half* Gl = (sel == 0 ? g_ql : (sel == 1 ? g_kl : g_vl)) + (size_t)h * T_ * E2_;
    #pragma unroll
    for (int mt = 0; mt < 2; mt++)
        #pragma unroll
        for (int nt = 0; nt < 8; nt++) {
            int r = row0 + m0 + mt * 16 + (lane >> 2);
            int c = n0 + nt * 8 + (lane & 3) * 2;
            #pragma unroll
            for (int half2i = 0; half2i < 2; half2i++) {
                float v0 = acc[mt][nt][half2i * 2 + 0];
                float v1 = acc[mt][nt][half2i * 2 + 1];
                __half h0 = __float2half_rn(v0), h1 = __float2half_rn(v1);
                __half l0 = __float2half_rn(v0 - __half2float(h0));
                __half l1 = __float2half_rn(v1 - __half2float(h1));
                size_t o = (size_t)(r + half2i * 8) * E2_ + c;
                *(uint32_t*)&Gh[o] = packh2(h0, h1);
                *(uint32_t*)&Gl[o] = packh2(l0, l1);
            }
        }
}

// ---------------- fix-up: recompute 16 state rows with W_s (fp32) ------------
__global__ void __launch_bounds__(128) proj_fix(const float* __restrict__ X,
                                                const float* __restrict__ Wqs,
                                                const float* __restrict__ Wks,
                                                const float* __restrict__ Wvs) {
    __shared__ float xs[512][4];
    int h = blockIdx.x;
    int z = blockIdx.y;
    int g = blockIdx.z;
    const float* Ws = z == 0 ? Wqs : (z == 1 ? Wks : Wvs);
    __half* Gh = (z == 0 ? g_qh : (z == 1 ? g_kh : g_vh));
    __half* Gl = (z == 0 ? g_ql : (z == 1 ? g_kl : g_vl));
    int e = threadIdx.x;
    const float* Wp = Ws + (size_t)h * DIM_ * E2_ + e;
    float acc[4] = {};
    for (int d0 = 0; d0 < DIM_; d0 += 512) {
        __syncthreads();
        for (int l = threadIdx.x; l < 4 * 512; l += 128) {
            int ti = l >> 9;
            int c  = l & 511;
            int tok = g * 4 + ti;
            int t  = tok < 8 ? tok : 2032 + tok;
            xs[c][ti] = X[(size_t)t * DIM_ + d0 + c];
        }
        __syncthreads();
        for (int c = 0; c < 512; c++) {
            float w = Wp[(size_t)(d0 + c) * E2_];
            float4 x0 = *(const float4*)&xs[c][0];
            acc[0] = fmaf(x0.x, w, acc[0]);
            acc[1] = fmaf(x0.y, w, acc[1]);
            acc[2] = fmaf(x0.z, w, acc[2]);
            acc[3] = fmaf(x0.w, w, acc[3]);
        }
    }
    #pragma unroll
    for (int ti = 0; ti < 4; ti++) {
        int tok = g * 4 + ti;
        int t = tok < 8 ? tok : 2032 + tok;
        size_t idx = (size_t)h * T_ * E2_ + (size_t)t * E2_ + e;
        float v = acc[ti];
        __half hi = __float2half_rn(v);
        Gh[idx] = hi;
        Gl[idx] = __float2half_rn(v - __half2float(hi));
    }
}

// ---------------- flash attention via mma.sync, 2 CTAs/SM --------------------
// Q staged inside stage-1 buffer (Q lives in regs after prologue).
#define AT_ROWB  144
#define AT_VROWB 272
#define AT_KH    0
#define AT_KL    (64*AT_ROWB)                   // 9216
#define AT_VH    (2*64*AT_ROWB)                 // 18432
#define AT_VL    (2*64*AT_ROWB + 64*AT_VROWB)   // 35840
#define AT_STAGE (2*64*AT_ROWB + 2*64*AT_VROWB) // 53248
#define AT_SMEM  (2*AT_STAGE)                   // 106496

__global__ void __launch_bounds__(256, 2) attn_kernel() {
    extern __shared__ char smc[];
    uint32_t sbase = smem_to_u32(smc);
    int tid = threadIdx.x, lane = tid & 31, wid = tid >> 5;
    int bid = (int)blockIdx.x;
    int qb = 15 - (bid >> 5);
    int rem = bid & 31;
    int h = rem >> 1;
    int which = rem & 1;
    int t0 = qb * 128;

    size_t hbase = (size_t)h * T_ * E2_;
    const char* Qh = (const char*)(g_qh + hbase + (size_t)t0 * E2_ + which * DK_);
    const char* Ql = (const char*)(g_ql + hbase + (size_t)t0 * E2_ + which * DK_);
    const char* Kh = (const char*)(g_kh + hbase + which * DK_);
    const char* Kl = (const char*)(g_kl + hbase + which * DK_);
    const char* Vh = (const char*)(g_vh + hbase);
    const char* Vl = (const char*)(g_vl + hbase);
    float* Ao = (which ? g_att2 : g_att1) + hbase + (size_t)t0 * E2_;

    auto issue_kv = [&](int kb, int b) {
        uint32_t sb = sbase + b * AT_STAGE;
        size_t kofs = (size_t)kb * 64 * 256;
        #pragma unroll
        for (int i = 0; i < 2; i++) {
            int l = tid + i * 256;
            int row = l >> 3, seg = l & 7;
            uint32_t so = row * AT_ROWB + seg * 16;
            size_t go = kofs + (size_t)row * 256 + seg * 16;
            CP_ASYNC16(sb + AT_KH + so, Kh + go);
            CP_ASYNC16(sb + AT_KL + so, Kl + go);
        }
        #pragma unroll
        for (int i = 0; i < 4; i++) {
            int l = tid + i * 256;
            int row = l >> 4, seg = l & 15;
            uint32_t so = row * AT_VROWB + seg * 16;
            size_t go = kofs + (size_t)row * 256 + seg * 16;
            CP_ASYNC16(sb + AT_VH + so, Vh + go);
            CP_ASYNC16(sb + AT_VL + so, Vl + go);
        }
        CP_COMMIT();
    };

    // kb=0 K/V into stage 0; Q into stage 1 (hi at +0, lo at +18432)
    issue_kv(0, 0);
    {
        uint32_t qbase = sbase + AT_STAGE;
        #pragma unroll
        for (int i = 0; i < 4; i++) {
            int l = tid + i * 256;
            int row = l >> 3, seg = l & 7;
            uint32_t so = row * AT_ROWB + seg * 16;
            size_t go = (size_t)row * 256 + seg * 16;
            CP_ASYNC16(qbase + so, Qh + go);
            CP_ASYNC16(qbase + 128 * AT_ROWB + so, Ql + go);
        }
        CP_COMMIT();
    }
    asm volatile("cp.async.wait_group 0;" ::: "memory");
    __syncthreads();

    // Q fragments (persist; stage-1 buffer becomes free after this)
    uint32_t qh[4][4], ql[4][4];
    {
        uint32_t qbase = sbase + AT_STAGE;
        #pragma unroll
        for (int kt = 0; kt < 4; kt++) {
            uint32_t off = (uint32_t)(wid * 16 + (lane & 15)) * AT_ROWB
                         + (kt * 16 + (lane >> 4) * 8) * 2;
            LDSM4(qh[kt], qbase + off);
            LDSM4(ql[kt], qbase + 128 * AT_ROWB + off);
        }
    }
    __syncthreads();   // all warps done reading Q before stage-1 reuse

    float o[16][4] = {};
    float mA = -INFINITY, mB = -INFINITY, lA = 0.f, lB = 0.f;
    int nkb = 2 * qb + 2;

    for (int kb = 0; kb < nkb; kb++) {
        int b = kb & 1;
        if (kb + 1 < nkb) {
            issue_kv(kb + 1, b ^ 1);
            asm volatile("cp.async.wait_group 1;" ::: "memory");
        } else {
            asm volatile("cp.async.wait_group 0;" ::: "memory");
        }
        __syncthreads();

        uint32_t sb = sbase + b * AT_STAGE;

        // ---- S = Q K^T, split hi/lo; K fragments loaded per n-pair ----
        float s[8][4] = {};
        #pragma unroll
        for (int kt = 0; kt < 4; kt++) {
            #pragma unroll
            for (int np = 0; np < 4; np++) {
                uint32_t off = (uint32_t)(np * 16 + (lane & 7) + ((lane >> 4) & 1) * 8) * AT_ROWB
                             + (kt * 16 + ((lane >> 3) & 1) * 8) * 2;
                uint32_t kfh[4], kfl[4];
                LDSM4(kfh, sb + AT_KH + off);
                LDSM4(kfl, sb + AT_KL + off);
                #pragma unroll
                for (int sub = 0; sub < 2; sub++) {
                    int nt = np * 2 + sub;
                    MMA16816(s[nt], qh[kt], &kfh[sub * 2]);
                    MMA16816(s[nt], ql[kt], &kfh[sub * 2]);
                    MMA16816(s[nt], qh[kt], &kfl[sub * 2]);
                }
            }
        }

        bool diag = (kb >= 2 * qb);
        int rA = t0 + wid * 16 + (lane >> 2);
        #pragma unroll
        for (int nt = 0; nt < 8; nt++)
            #pragma unroll
            for (int e = 0; e < 4; e++) {
                float v = s[nt][e] * 0.125f;
                if (diag) {
                    int jc = kb * 64 + nt * 8 + (lane & 3) * 2 + (e & 1);
                    int ir = rA + (e >> 1) * 8;
                    if (jc > ir) v = -1e30f;
                }
                s[nt][e] = v;
            }

        float rmA = -INFINITY, rmB = -INFINITY;
        #pragma unroll
        for (int nt = 0; nt < 8; nt++) {
            rmA = fmaxf(rmA, fmaxf(s[nt][0], s[nt][1]));
            rmB = fmaxf(rmB, fmaxf(s[nt][2], s[nt][3]));
        }
        rmA = fmaxf(rmA, __shfl_xor_sync(0xffffffffu, rmA, 1));
        rmA = fmaxf(rmA, __shfl_xor_sync(0xffffffffu, rmA, 2));
        rmB = fmaxf(rmB, __shfl_xor_sync(0xffffffffu, rmB, 1));
        rmB = fmaxf(rmB, __shfl_xor_sync(0xffffffffu, rmB, 2));
        float nmA = fmaxf(mA, rmA), nmB = fmaxf(mB, rmB);
        float aA = __expf(mA - nmA), aB = __expf(mB - nmB);
        mA = nmA; mB = nmB;
        float rsA = 0.f, rsB = 0.f;
        #pragma unroll
        for (int nt = 0; nt < 8; nt++) {
            s[nt][0] = __expf(s[nt][0] - nmA);
            s[nt][1] = __expf(s[nt][1] - nmA);
            s[nt][2] = __expf(s[nt][2] - nmB);
            s[nt][3] = __expf(s[nt][3] - nmB);
            rsA += s[nt][0] + s[nt][1];
            rsB += s[nt][2] + s[nt][3];
        }
        rsA += __shfl_xor_sync(0xffffffffu, rsA, 1);
        rsA += __shfl_xor_sync(0xffffffffu, rsA, 2);
        rsB += __shfl_xor_sync(0xffffffffu, rsB, 1);
        rsB += __shfl_xor_sync(0xffffffffu, rsB, 2);
        lA = lA * aA + rsA;
        lB = lB * aB + rsB;
        #pragma unroll
        for (int nt = 0; nt < 16; nt++) {
            o[nt][0] *= aA; o[nt][1] *= aA;
            o[nt][2] *= aB; o[nt][3] *= aB;
        }

        uint32_t ph[4][4], pl[4][4];
        #pragma unroll
        for (int kt = 0; kt < 4; kt++)
            #pragma unroll
            for (int half16 = 0; half16 < 2; half16++) {
                float* e = s[2 * kt + half16];
                __half h0 = __float2half_rn(e[0]), h1 = __float2half_rn(e[1]);
                __half h2 = __float2half_rn(e[2]), h3 = __float2half_rn(e[3]);
                ph[kt][half16 * 2 + 0] = packh2(h0, h1);
                ph[kt][half16 * 2 + 1] = packh2(h2, h3);
                pl[kt][half16 * 2 + 0] = packh2(__float2half_rn(e[0] - __half2float(h0)),
                                                __float2half_rn(e[1] - __half2float(h1)));
                pl[kt][half16 * 2 + 1] = packh2(__float2half_rn(e[2] - __half2float(h2)),
                                                __float2half_rn(e[3] - __half2float(h3)));
            }

        #pragma unroll
        for (int kt = 0; kt < 4; kt++) {
            #pragma unroll
            for (int vn = 0; vn < 8; vn++) {
                uint32_t off = (uint32_t)(kt * 16 + (lane & 15)) * AT_VROWB
                             + (vn * 16 + (lane >> 4) * 8) * 2;
                uint32_t vf[4], vg[4];
                LDSMT4(vf, sb + AT_VH + off);
                LDSMT4(vg, sb + AT_VL + off);
                MMA16816(o[2 * vn + 0], ph[kt], &vf[0]);
                MMA16816(o[2 * vn + 0], pl[kt], &vf[0]);
                MMA16816(o[2 * vn + 0], ph[kt], &vg[0]);
                MMA16816(o[2 * vn + 1], ph[kt], &vf[2]);
                MMA16816(o[2 * vn + 1], pl[kt], &vf[2]);
                MMA16816(o[2 * vn + 1], ph[kt], &vg[2]);
            }
        }
        __syncthreads();   // all reads of buffer b done before next issue overwrites
    }

    float invA = 1.f / lA, invB = 1.f / lB;
    int rloc = wid * 16 + (lane >> 2);
    #pragma unroll
    for (int nt = 0; nt < 16; nt++) {
        int c = nt * 8 + (lane & 3) * 2;
        *(float2*)&Ao[(size_t)rloc * E2_ + c] = make_float2(o[nt][0] * invA, o[nt][1] * invA);
        *(float2*)&Ao[(size_t)(rloc + 8) * E2_ + c] = make_float2(o[nt][2] * invB, o[nt][3] * invB);
    }
}

// ---------------- combine + layernorm + scale --------------------------------
__global__ void __launch_bounds__(128) final_kernel(const float* __restrict__ gamma,
                                                    const float* __restrict__ beta,
                                                    float* __restrict__ Out) {
    int h = blockIdx.x >> 11;
    int t = blockIdx.x & 2047;
    int e = threadIdx.x;
    size_t base = ((size_t)h * T_ + t) * E2_;
    float a1 = g_att1[base + e];
    float a2 = g_att2[base + e];
    float v = a1 - g_lam[h] * a2;

    float s1 = v, s2 = v * v;
    #pragma unroll
    for (int off = 16; off; off >>= 1) {
        s1 += __shfl_xor_sync(0xffffffffu, s1, off);
        s2 += __shfl_xor_sync(0xffffffffu, s2, off);
    }
    __shared__ float red[8];
    int w = e >> 5, lane = e & 31;
    if (lane == 0) { red[w] = s1; red[4 + w] = s2; }
    __syncthreads();
    float sum = red[0] + red[1] + red[2] + red[3];
    float sq  = red[4] + red[5] + red[6] + red[7];
    float mu  = sum * (1.f / 128.f);
    float var = fmaxf(sq * (1.f / 128.f) - mu * mu, 0.f);
    float nv  = (v - mu) * rsqrtf(var + EPS_);
    Out[base + e] = (nv * gamma[h * E2_ + e] + beta[h * E2_ + e]) * OUT_SCALE_;
}

// ---------------- launch -----------------------------------------------------
extern "C" void kernel_launch(void* const* d_in, const int* in_sizes, int n_in,
                              void* d_out, int out_size) {
    const float* x   = (const float*)d_in[0];
    const float* Wq  = (const float*)d_in[1];
    const float* Wk  = (const float*)d_in[2];
    const float* Wv  = (const float*)d_in[3];
    const float* Wqs = (const float*)d_in[4];
    const float* Wks = (const float*)d_in[5];
    const float* Wvs = (const float*)d_in[6];
    const float* lq1 = (const float*)d_in[7];
    const float* lq2 = (const float*)d_in[8];
    const float* lk1 = (const float*)d_in[9];
    const float* lk2 = (const float*)d_in[10];
    const float* gam = (const float*)d_in[11];
    const float* bet = (const float*)d_in[12];
    float* out = (float*)d_out;

    size_t psmem = 2 * PRJ_STAGEB;   // 110592
    cudaFuncSetAttribute(proj_mma, cudaFuncAttributeMaxDynamicSharedMemorySize, (int)psmem);
    cudaFuncSetAttribute(attn_kernel, cudaFuncAttributeMaxDynamicSharedMemorySize, AT_SMEM);

    lam_kernel<<<1, 32>>>(lq1, lq2, lk1, lk2);
    split_x<<<T_, 256>>>(x);
    transp_w<<<dim3(64, 4, 48), 256>>>(Wq, Wk, Wv);
    proj_mma<<<dim3(16, 16, 3), 256, psmem>>>();
    proj_fix<<<dim3(16, 3, 4), 128>>>(x, Wqs, Wks, Wvs);
    attn_kernel<<<512, 256, AT_SMEM>>>();
    final_kernel<<<32768, 128>>>(gam, bet, out);
}

// round 13
// speedup vs baseline: 1.0508x; 1.0508x over previous
#include <cuda_runtime.h>
#include <cuda_fp16.h>
#include <math.h>
#include <cstdint>

#define H_   16
#define T_   2048
#define DIM_ 2048
#define DK_  64
#define E2_  128
#define LAMBDA_INIT_ 0.6192834728526787f
#define OUT_SCALE_   0.3807165271473213f
#define EPS_ 1e-5f

// ---------------- scratch ----------------------------------------------------
__device__ float g_att1[H_*T_*E2_];
__device__ float g_att2[H_*T_*E2_];
__device__ float g_lam[H_];
__device__ __align__(256) __half g_xhi[T_*DIM_];
__device__ __align__(256) __half g_wthi[3*H_*E2_*DIM_];   // [sel][h][e][d]
__device__ __align__(256) __half g_wtlo[3*H_*E2_*DIM_];
__device__ __align__(256) __half g_qh[H_*T_*E2_];
__device__ __align__(256) __half g_ql[H_*T_*E2_];
__device__ __align__(256) __half g_kh[H_*T_*E2_];
__device__ __align__(256) __half g_kl[H_*T_*E2_];
__device__ __align__(256) __half g_vh[H_*T_*E2_];
__device__ __align__(256) __half g_vl[H_*T_*E2_];

// ---------------- helpers ----------------------------------------------------
__device__ __forceinline__ uint32_t smem_to_u32(const void* p) {
    uint32_t a;
    asm("{ .reg .u64 t; cvta.to.shared.u64 t, %1; cvt.u32.u64 %0, t; }" : "=r"(a) : "l"(p));
    return a;
}
#define LDSM4(r, addr) \
    asm volatile("ldmatrix.sync.aligned.m8n8.x4.shared.b16 {%0,%1,%2,%3}, [%4];" \
        : "=r"((r)[0]), "=r"((r)[1]), "=r"((r)[2]), "=r"((r)[3]) : "r"(addr))
#define LDSMT4(r, addr) \
    asm volatile("ldmatrix.sync.aligned.m8n8.x4.trans.shared.b16 {%0,%1,%2,%3}, [%4];" \
        : "=r"((r)[0]), "=r"((r)[1]), "=r"((r)[2]), "=r"((r)[3]) : "r"(addr))
#define MMA16816(c, a, b) \
    asm volatile("mma.sync.aligned.m16n8k16.row.col.f32.f16.f16.f32 " \
        "{%0,%1,%2,%3}, {%4,%5,%6,%7}, {%8,%9}, {%0,%1,%2,%3};" \
        : "+f"((c)[0]), "+f"((c)[1]), "+f"((c)[2]), "+f"((c)[3]) \
        : "r"((a)[0]), "r"((a)[1]), "r"((a)[2]), "r"((a)[3]), "r"((b)[0]), "r"((b)[1]))
#define CP_ASYNC16(sa, ga) \
    asm volatile("cp.async.cg.shared.global [%0], [%1], 16;" :: "r"(sa), "l"(ga))
#define CP_COMMIT() asm volatile("cp.async.commit_group;" ::: "memory")

__device__ __forceinline__ uint32_t packh2(__half a, __half b) {
    __half2 h = __halves2half2(a, b);
    return *(uint32_t*)&h;
}

// ---------------- lambda -----------------------------------------------------
__global__ void lam_kernel(const float* __restrict__ lq1, const float* __restrict__ lq2,
                           const float* __restrict__ lk1, const float* __restrict__ lk2) {
    int h = threadIdx.x;
    if (h < H_) {
        float d1 = 0.f, d2 = 0.f;
        for (int d = 0; d < DK_; d++) {
            d1 += lq1[h*DK_ + d] * lk1[h*DK_ + d];
            d2 += lq2[h*DK_ + d] * lk2[h*DK_ + d];
        }
        g_lam[h] = expf(d1) - expf(d2) + LAMBDA_INIT_;
    }
}

// ---------------- prep: X to fp16 (hi only) ----------------------------------
__global__ void __launch_bounds__(256) split_x(const float* __restrict__ X) {
    int t = blockIdx.x;
    const float* xp = X + (size_t)t * DIM_;
    __half* hp = g_xhi + (size_t)t * DIM_;
    for (int j = threadIdx.x; j < DIM_; j += 256)
        hp[j] = __float2half_rn(xp[j]);
}

// ---------------- prep: transpose + split W ----------------------------------
__global__ void __launch_bounds__(256) transp_w(const float* __restrict__ Wq,
                                                const float* __restrict__ Wk,
                                                const float* __restrict__ Wv) {
    __shared__ float tile[32][33];
    int hs = blockIdx.z;
    int sel = hs >> 4, h = hs & 15;
    const float* W = sel == 0 ? Wq : (sel == 1 ? Wk : Wv);
    int d0 = blockIdx.x * 32;
    int e0 = blockIdx.y * 32;
    int tx = threadIdx.x & 31, ty = threadIdx.x >> 5;
    #pragma unroll
    for (int i = 0; i < 4; i++) {
        int d = d0 + ty + i * 8;
        tile[ty + i * 8][tx] = W[((size_t)h * DIM_ + d) * E2_ + e0 + tx];
    }
    __syncthreads();
    #pragma unroll
    for (int i = 0; i < 4; i++) {
        int e = e0 + ty + i * 8;
        float v = tile[tx][ty + i * 8];
        __half hi = __float2half_rn(v);
        size_t idx = ((size_t)hs * E2_ + e) * DIM_ + d0 + tx;
        g_wthi[idx] = hi;
        g_wtlo[idx] = __float2half_rn(v - __half2float(hi));
    }
}

// ---------------- projection via mma.sync: Xhi*(Whi+Wlo) (round-9 config) ----
#define PRJ_ROWB   144
#define PRJ_TILEB  (128*PRJ_ROWB)        // 18432
#define PRJ_STAGEB (3*PRJ_TILEB)         // 55296
#define PRJ_NSTG   32                    // 2048 / 64

__global__ void __launch_bounds__(256, 2) proj_mma() {
    extern __shared__ char smc[];
    uint32_t sbase = smem_to_u32(smc);
    int tid = threadIdx.x, lane = tid & 31, wid = tid >> 5;
    int tblk = blockIdx.x, h = blockIdx.y, sel = blockIdx.z;
    int row0 = tblk * 128;

    const char* gA0 = (const char*)g_xhi + (size_t)row0 * (DIM_ * 2);
    size_t wofs = (size_t)(sel * H_ + h) * E2_ * (DIM_ * 2);
    const char* gA1 = (const char*)g_wthi + wofs;
    const char* gA2 = (const char*)g_wtlo + wofs;

    int m0 = (wid >> 1) * 32, n0 = (wid & 1) * 64;
    float acc[2][8][4] = {};

    auto issue = [&](int s, int b) {
        uint32_t sb = sbase + b * PRJ_STAGEB;
        size_t k0b = (size_t)s * 128;
        #pragma unroll
        for (int i = 0; i < 4; i++) {
            int l = tid + i * 256;
            int row = l >> 3, seg = l & 7;
            size_t gofs = (size_t)row * (DIM_ * 2) + k0b + seg * 16;
            uint32_t sofs = row * PRJ_ROWB + seg * 16;
            CP_ASYNC16(sb + 0 * PRJ_TILEB + sofs, gA0 + gofs);
            CP_ASYNC16(sb + 1 * PRJ_TILEB + sofs, gA1 + gofs);
            CP_ASYNC16(sb + 2 * PRJ_TILEB + sofs, gA2 + gofs);
        }
        CP_COMMIT();
    };

    issue(0, 0);
    for (int s = 0; s < PRJ_NSTG; s++) {
        int b = s & 1;
        if (s < PRJ_NSTG - 1) issue(s + 1, b ^ 1);
        if (s < PRJ_NSTG - 1) asm volatile("cp.async.wait_group 1;" ::: "memory");
        else                  asm volatile("cp.async.wait_group 0;" ::: "memory");
        __syncthreads();

        uint32_t sA  = sbase + b * PRJ_STAGEB;
        uint32_t sBh = sA + PRJ_TILEB;
        uint32_t sBl = sBh + PRJ_TILEB;
        #pragma unroll
        for (int kk = 0; kk < 64; kk += 16) {
            uint32_t ah[2][4];
            #pragma unroll
            for (int mt = 0; mt < 2; mt++) {
                uint32_t off = (uint32_t)(m0 + mt * 16 + (lane & 15)) * PRJ_ROWB
                             + (kk + (lane >> 4) * 8) * 2;
                LDSM4(ah[mt], sA + off);
            }
            uint32_t bh[4][4], bl[4][4];
            #pragma unroll
            for (int np = 0; np < 4; np++) {
                uint32_t off = (uint32_t)(n0 + np * 16 + (lane & 7) + ((lane >> 4) & 1) * 8) * PRJ_ROWB
                             + (kk + ((lane >> 3) & 1) * 8) * 2;
                LDSM4(bh[np], sBh + off);
                LDSM4(bl[np], sBl + off);
            }
            #pragma unroll
            for (int mt = 0; mt < 2; mt++)
                #pragma unroll
                for (int nt = 0; nt < 8; nt++) {
                    uint32_t* bhp = &bh[nt >> 1][(nt & 1) * 2];
                    uint32_t* blp = &bl[nt >> 1][(nt & 1) * 2];
                    MMA16816(acc[mt][nt], ah[mt], bhp);
                    MMA16816(acc[mt][nt], ah[mt], blp);
                }
        }
        __syncthreads();
    }

    __half* Gh = (sel == 0 ? g_qh : (sel == 1 ? g_kh : g_vh)) + (size_t)h * T_ * E2_;
    __half* Gl = (sel == 0 ? g_ql : (sel == 1 ? g_kl : g_vl)) + (size_t)h * T_ * E2_;
    #pragma unroll
    for (int mt = 0; mt < 2; mt++)
        #pragma unroll
        for (int nt = 0; nt < 8; nt++) {
            int r = row0 + m0 + mt * 16 + (lane >> 2);
            int c = n0 + nt * 8 + (lane & 3) * 2;
            #pragma unroll
            for (int half2i = 0; half2i < 2; half2i++) {
                float v0 = acc[mt][nt][half2i * 2 + 0];
                float v1 = acc[mt][nt][half2i * 2 + 1];
                __half h0 = __float2half_rn(v0), h1 = __float2half_rn(v1);
                __half l0 = __float2half_rn(v0 - __half2float(h0));
                __half l1 = __float2half_rn(v1 - __half2float(h1));
                size_t o = (size_t)(r + half2i * 8) * E2_ + c;
                *(uint32_t*)&Gh[o] = packh2(h0, h1);
                *(uint32_t*)&Gl[o] = packh2(l0, l1);
            }
        }
}

// ---------------- fix-up: 16 state rows with W_s, 48 blocks, d-split ---------
// 256 threads: e = tid&127 (column), half = tid>>7 splits the d-reduction.
__global__ void __launch_bounds__(256) proj_fix(const float* __restrict__ X,
                                                const float* __restrict__ Wqs,
                                                const float* __restrict__ Wks,
                                                const float* __restrict__ Wvs) {
    __shared__ float xs[256][20];        // [d-chunk][token], padded (16B aligned rows)
    __shared__ float part[16][128];
    int h = blockIdx.x;
    int z = blockIdx.y;
    const float* Ws = z == 0 ? Wqs : (z == 1 ? Wks : Wvs);
    __half* Gh = (z == 0 ? g_qh : (z == 1 ? g_kh : g_vh));
    __half* Gl = (z == 0 ? g_ql : (z == 1 ? g_kl : g_vl));
    int tid = threadIdx.x;
    int e = tid & 127, half = tid >> 7;
    const float* Wp = Ws + (size_t)h * DIM_ * E2_ + e;
    float acc[16] = {};
    for (int d0 = 0; d0 < DIM_; d0 += 256) {
        __syncthreads();
        for (int l = tid; l < 16 * 256; l += 256) {
            int ti = l >> 8;
            int c  = l & 255;
            int t  = ti < 8 ? ti : 2032 + ti;
            xs[c][ti] = X[(size_t)t * DIM_ + d0 + c];
        }
        __syncthreads();
        for (int i = 0; i < 128; i++) {
            int c = 2 * i + half;                    // even/odd split across halves
            float w = Wp[(size_t)(d0 + c) * E2_];
            float4 x0 = *(const float4*)&xs[c][0];
            float4 x1 = *(const float4*)&xs[c][4];
            float4 x2 = *(const float4*)&xs[c][8];
            float4 x3 = *(const float4*)&xs[c][12];
            acc[0]  = fmaf(x0.x, w, acc[0]);   acc[1]  = fmaf(x0.y, w, acc[1]);
            acc[2]  = fmaf(x0.z, w, acc[2]);   acc[3]  = fmaf(x0.w, w, acc[3]);
            acc[4]  = fmaf(x1.x, w, acc[4]);   acc[5]  = fmaf(x1.y, w, acc[5]);
            acc[6]  = fmaf(x1.z, w, acc[6]);   acc[7]  = fmaf(x1.w, w, acc[7]);
            acc[8]  = fmaf(x2.x, w, acc[8]);   acc[9]  = fmaf(x2.y, w, acc[9]);
            acc[10] = fmaf(x2.z, w, acc[10]);  acc[11] = fmaf(x2.w, w, acc[11]);
            acc[12] = fmaf(x3.x, w, acc[12]);  acc[13] = fmaf(x3.y, w, acc[13]);
            acc[14] = fmaf(x3.z, w, acc[14]);  acc[15] = fmaf(x3.w, w, acc[15]);
        }
    }
    __syncthreads();
    if (half == 1) {
        #pragma unroll
        for (int ti = 0; ti < 16; ti++) part[ti][e] = acc[ti];
    }
    __syncthreads();
    if (half == 0) {
        #pragma unroll
        for (int ti = 0; ti < 16; ti++) {
            int t = ti < 8 ? ti : 2032 + ti;
            size_t idx = (size_t)h * T_ * E2_ + (size_t)t * E2_ + e;
            float v = acc[ti] + part[ti][e];
            __half hi = __float2half_rn(v);
            Gh[idx] = hi;
            Gl[idx] = __float2half_rn(v - __half2float(hi));
        }
    }
}

// ---------------- flash attention via mma.sync (round-9 version) -------------
#define AT_ROWB  144
#define AT_VROWB 272
#define AT_QH    0
#define AT_QL    (128*AT_ROWB)
#define AT_ST0   (2*128*AT_ROWB)
#define AT_KH    0
#define AT_KL    (64*AT_ROWB)
#define AT_VH    (2*64*AT_ROWB)
#define AT_VL    (2*64*AT_ROWB + 64*AT_VROWB)
#define AT_STAGE (2*64*AT_ROWB + 2*64*AT_VROWB)
#define AT_SMEM  (AT_ST0 + 2*AT_STAGE)     // 143360

__global__ void __launch_bounds__(256) attn_kernel() {
    extern __shared__ char smc[];
    uint32_t sbase = smem_to_u32(smc);
    int tid = threadIdx.x, lane = tid & 31, wid = tid >> 5;
    int bid = (int)blockIdx.x;
    int qb = 15 - (bid >> 5);
    int rem = bid & 31;
    int h = rem >> 1;
    int which = rem & 1;
    int t0 = qb * 128;

    size_t hbase = (size_t)h * T_ * E2_;
    const char* Qh = (const char*)(g_qh + hbase + (size_t)t0 * E2_ + which * DK_);
    const char* Ql = (const char*)(g_ql + hbase + (size_t)t0 * E2_ + which * DK_);
    const char* Kh = (const char*)(g_kh + hbase + which * DK_);
    const char* Kl = (const char*)(g_kl + hbase + which * DK_);
    const char* Vh = (const char*)(g_vh + hbase);
    const char* Vl = (const char*)(g_vl + hbase);
    float* Ao = (which ? g_att2 : g_att1) + hbase + (size_t)t0 * E2_;

    #pragma unroll
    for (int i = 0; i < 4; i++) {
        int l = tid + i * 256;
        int row = l >> 3, seg = l & 7;
        uint32_t so = row * AT_ROWB + seg * 16;
        size_t go = (size_t)row * 256 + seg * 16;
        CP_ASYNC16(sbase + AT_QH + so, Qh + go);
        CP_ASYNC16(sbase + AT_QL + so, Ql + go);
    }
    CP_COMMIT();

    auto issue_kv = [&](int kb, int b) {
        uint32_t sb = sbase + AT_ST0 + b * AT_STAGE;
        size_t kofs = (size_t)kb * 64 * 256;
        #pragma unroll
        for (int i = 0; i < 2; i++) {
            int l = tid + i * 256;
            int row = l >> 3, seg = l & 7;
            uint32_t so = row * AT_ROWB + seg * 16;
            size_t go = kofs + (size_t)row * 256 + seg * 16;
            CP_ASYNC16(sb + AT_KH + so, Kh + go);
            CP_ASYNC16(sb + AT_KL + so, Kl + go);
        }
        #pragma unroll
        for (int i = 0; i < 4; i++) {
            int l = tid + i * 256;
            int row = l >> 4, seg = l & 15;
            uint32_t so = row * AT_VROWB + seg * 16;
            size_t go = kofs + (size_t)row * 256 + seg * 16;
            CP_ASYNC16(sb + AT_VH + so, Vh + go);
            CP_ASYNC16(sb + AT_VL + so, Vl + go);
        }
        CP_COMMIT();
    };

    issue_kv(0, 0);
    asm volatile("cp.async.wait_group 1;" ::: "memory");
    __syncthreads();

    uint32_t qh[4][4], ql[4][4];
    #pragma unroll
    for (int kt = 0; kt < 4; kt++) {
        uint32_t off = (uint32_t)(wid * 16 + (lane & 15)) * AT_ROWB
                     + (kt * 16 + (lane >> 4) * 8) * 2;
        LDSM4(qh[kt], sbase + AT_QH + off);
        LDSM4(ql[kt], sbase + AT_QL + off);
    }

    float o[16][4] = {};
    float mA = -INFINITY, mB = -INFINITY, lA = 0.f, lB = 0.f;
    int nkb = 2 * qb + 2;

    for (int kb = 0; kb < nkb; kb++) {
        int b = kb & 1;
        if (kb + 1 < nkb) {
            issue_kv(kb + 1, b ^ 1);
            asm volatile("cp.async.wait_group 1;" ::: "memory");
        } else {
            asm volatile("cp.async.wait_group 0;" ::: "memory");
        }
        __syncthreads();

        uint32_t sb = sbase + AT_ST0 + b * AT_STAGE;

        float s[8][4] = {};
        #pragma unroll
        for (int kt = 0; kt < 4; kt++) {
            uint32_t kfh[4][4], kfl[4][4];
            #pragma unroll
            for (int np = 0; np < 4; np++) {
                uint32_t off = (uint32_t)(np * 16 + (lane & 7) + ((lane >> 4) & 1) * 8) * AT_ROWB
                             + (kt * 16 + ((lane >> 3) & 1) * 8) * 2;
                LDSM4(kfh[np], sb + AT_KH + off);
                LDSM4(kfl[np], sb + AT_KL + off);
            }
            #pragma unroll
            for (int nt = 0; nt < 8; nt++) {
                uint32_t* bh = &kfh[nt >> 1][(nt & 1) * 2];
                uint32_t* bl = &kfl[nt >> 1][(nt & 1) * 2];
                MMA16816(s[nt], qh[kt], bh);
                MMA16816(s[nt], ql[kt], bh);
                MMA16816(s[nt], qh[kt], bl);
            }
        }

        bool diag = (kb >= 2 * qb);
        int rA = t0 + wid * 16 + (lane >> 2);
        #pragma unroll
        for (int nt = 0; nt < 8; nt++)
            #pragma unroll
            for (int e = 0; e < 4; e++) {
                float v = s[nt][e] * 0.125f;
                if (diag) {
                    int jc = kb * 64 + nt * 8 + (lane & 3) * 2 + (e & 1);
                    int ir = rA + (e >> 1) * 8;
                    if (jc > ir) v = -1e30f;
                }
                s[nt][e] = v;
            }

        float rmA = -INFINITY, rmB = -INFINITY;
        #pragma unroll
        for (int nt = 0; nt < 8; nt++) {
            rmA = fmaxf(rmA, fmaxf(s[nt][0], s[nt][1]));
            rmB = fmaxf(rmB, fmaxf(s[nt][2], s[nt][3]));
        }
        rmA = fmaxf(rmA, __shfl_xor_sync(0xffffffffu, rmA, 1));
        rmA = fmaxf(rmA, __shfl_xor_sync(0xffffffffu, rmA, 2));
        rmB = fmaxf(rmB, __shfl_xor_sync(0xffffffffu, rmB, 1));
        rmB = fmaxf(rmB, __shfl_xor_sync(0xffffffffu, rmB, 2));
        float nmA = fmaxf(mA, rmA), nmB = fmaxf(mB, rmB);
        float aA = __expf(mA - nmA), aB = __expf(mB - nmB);
        mA = nmA; mB = nmB;
        float rsA = 0.f, rsB = 0.f;
        #pragma unroll
        for (int nt = 0; nt < 8; nt++) {
            s[nt][0] = __expf(s[nt][0] - nmA);
            s[nt][1] = __expf(s[nt][1] - nmA);
            s[nt][2] = __expf(s[nt][2] - nmB);
            s[nt][3] = __expf(s[nt][3] - nmB);
            rsA += s[nt][0] + s[nt][1];
            rsB += s[nt][2] + s[nt][3];
        }
        rsA += __shfl_xor_sync(0xffffffffu, rsA, 1);
        rsA += __shfl_xor_sync(0xffffffffu, rsA, 2);
        rsB += __shfl_xor_sync(0xffffffffu, rsB, 1);
        rsB += __shfl_xor_sync(0xffffffffu, rsB, 2);
        lA = lA * aA + rsA;
        lB = lB * aB + rsB;
        #pragma unroll
        for (int nt = 0; nt < 16; nt++) {
            o[nt][0] *= aA; o[nt][1] *= aA;
            o[nt][2] *= aB; o[nt][3] *= aB;
        }

        uint32_t ph[4][4], pl[4][4];
        #pragma unroll
        for (int kt = 0; kt < 4; kt++)
            #pragma unroll
            for (int half16 = 0; half16 < 2; half16++) {
                float* e = s[2 * kt + half16];
                __half h0 = __float2half_rn(e[0]), h1 = __float2half_rn(e[1]);
                __half h2 = __float2half_rn(e[2]), h3 = __float2half_rn(e[3]);
                ph[kt][half16 * 2 + 0] = packh2(h0, h1);
                ph[kt][half16 * 2 + 1] = packh2(h2, h3);
                pl[kt][half16 * 2 + 0] = packh2(__float2half_rn(e[0] - __half2float(h0)),
                                                __float2half_rn(e[1] - __half2float(h1)));
                pl[kt][half16 * 2 + 1] = packh2(__float2half_rn(e[2] - __half2float(h2)),
                                                __float2half_rn(e[3] - __half2float(h3)));
            }

        #pragma unroll
        for (int kt = 0; kt < 4; kt++) {
            #pragma unroll
            for (int vn = 0; vn < 8; vn++) {
                uint32_t off = (uint32_t)(kt * 16 + (lane & 15)) * AT_VROWB
                             + (vn * 16 + (lane >> 4) * 8) * 2;
                uint32_t vf[4], vg[4];
                LDSMT4(vf, sb + AT_VH + off);
                LDSMT4(vg, sb + AT_VL + off);
                MMA16816(o[2 * vn + 0], ph[kt], &vf[0]);
                MMA16816(o[2 * vn + 0], pl[kt], &vf[0]);
                MMA16816(o[2 * vn + 0], ph[kt], &vg[0]);
                MMA16816(o[2 * vn + 1], ph[kt], &vf[2]);
                MMA16816(o[2 * vn + 1], pl[kt], &vf[2]);
                MMA16816(o[2 * vn + 1], ph[kt], &vg[2]);
            }
        }
        __syncthreads();
    }

    float invA = 1.f / lA, invB = 1.f / lB;
    int rloc = wid * 16 + (lane >> 2);
    #pragma unroll
    for (int nt = 0; nt < 16; nt++) {
        int c = nt * 8 + (lane & 3) * 2;
        *(float2*)&Ao[(size_t)rloc * E2_ + c] = make_float2(o[nt][0] * invA, o[nt][1] * invA);
        *(float2*)&Ao[(size_t)(rloc + 8) * E2_ + c] = make_float2(o[nt][2] * invB, o[nt][3] * invB);
    }
}

// ---------------- combine + layernorm + scale: 4 rows/block, float2 ----------
__global__ void __launch_bounds__(256) final_kernel(const float* __restrict__ gamma,
                                                    const float* __restrict__ beta,
                                                    float* __restrict__ Out) {
    int tid = threadIdx.x;
    int row = blockIdx.x * 4 + (tid >> 6);      // global row 0..32767
    int h = row >> 11;
    int t = row & 2047;
    int le = tid & 63;
    int e = le * 2;
    size_t base = ((size_t)h * T_ + t) * E2_;
    float lam = g_lam[h];
    float2 a1 = *(const float2*)&g_att1[base + e];
    float2 a2 = *(const float2*)&g_att2[base + e];
    float v0 = a1.x - lam * a2.x;
    float v1 = a1.y - lam * a2.y;

    float s1 = v0 + v1;
    float s2 = v0 * v0 + v1 * v1;
    #pragma unroll
    for (int off = 16; off; off >>= 1) {
        s1 += __shfl_xor_sync(0xffffffffu, s1, off);
        s2 += __shfl_xor_sync(0xffffffffu, s2, off);
    }
    __shared__ float red[2][8];
    int w = tid >> 5, lane = tid & 31;
    if (lane == 0) { red[0][w] = s1; red[1][w] = s2; }
    __syncthreads();
    int w0 = (tid >> 6) * 2;                    // this row's warp pair
    float sum = red[0][w0] + red[0][w0 + 1];
    float sq  = red[1][w0] + red[1][w0 + 1];
    float mu  = sum * (1.f / 128.f);
    float var = fmaxf(sq * (1.f / 128.f) - mu * mu, 0.f);
    float rstd = rsqrtf(var + EPS_);
    float2 g = *(const float2*)&gamma[h * E2_ + e];
    float2 bt = *(const float2*)&beta[h * E2_ + e];
    float2 outv;
    outv.x = ((v0 - mu) * rstd * g.x + bt.x) * OUT_SCALE_;
    outv.y = ((v1 - mu) * rstd * g.y + bt.y) * OUT_SCALE_;
    *(float2*)&Out[base + e] = outv;
}

// ---------------- launch -----------------------------------------------------
extern "C" void kernel_launch(void* const* d_in, const int* in_sizes, int n_in,
                              void* d_out, int out_size) {
    const float* x   = (const float*)d_in[0];
    const float* Wq  = (const float*)d_in[1];
    const float* Wk  = (const float*)d_in[2];
    const float* Wv  = (const float*)d_in[3];
    const float* Wqs = (const float*)d_in[4];
    const float* Wks = (const float*)d_in[5];
    const float* Wvs = (const float*)d_in[6];
    const float* lq1 = (const float*)d_in[7];
    const float* lq2 = (const float*)d_in[8];
    const float* lk1 = (const float*)d_in[9];
    const float* lk2 = (const float*)d_in[10];
    const float* gam = (const float*)d_in[11];
    const float* bet = (const float*)d_in[12];
    float* out = (float*)d_out;

    size_t psmem = 2 * PRJ_STAGEB;   // 110592
    cudaFuncSetAttribute(proj_mma, cudaFuncAttributeMaxDynamicSharedMemorySize, (int)psmem);
    cudaFuncSetAttribute(attn_kernel, cudaFuncAttributeMaxDynamicSharedMemorySize, AT_SMEM);

    lam_kernel<<<1, 32>>>(lq1, lq2, lk1, lk2);
    split_x<<<T_, 256>>>(x);
    transp_w<<<dim3(64, 4, 48), 256>>>(Wq, Wk, Wv);
    proj_mma<<<dim3(16, 16, 3), 256, psmem>>>();
    proj_fix<<<dim3(16, 3), 256>>>(x, Wqs, Wks, Wvs);
    attn_kernel<<<512, 256, AT_SMEM>>>();
    final_kernel<<<8192, 256>>>(gam, bet, out);
}

// round 15
// speedup vs baseline: 1.0825x; 1.0302x over previous
#include <cuda_runtime.h>
#include <cuda_fp16.h>
#include <math.h>
#include <cstdint>

#define H_   16
#define T_   2048
#define DIM_ 2048
#define DK_  64
#define E2_  128
#define LAMBDA_INIT_ 0.6192834728526787f
#define OUT_SCALE_   0.3807165271473213f
#define EPS_ 1e-5f

// ---------------- scratch ----------------------------------------------------
__device__ float g_att1[H_*T_*E2_];
__device__ float g_att2[H_*T_*E2_];
__device__ float g_lam[H_];
__device__ __align__(256) __half g_xhi[T_*DIM_];
__device__ __align__(256) __half g_wthi[3*H_*E2_*DIM_];   // [sel][h][e][d]
__device__ __align__(256) __half g_wtlo[3*H_*E2_*DIM_];
__device__ __align__(256) __half g_qh[H_*T_*E2_];
__device__ __align__(256) __half g_ql[H_*T_*E2_];
__device__ __align__(256) __half g_kh[H_*T_*E2_];
__device__ __align__(256) __half g_kl[H_*T_*E2_];
__device__ __align__(256) __half g_vh[H_*T_*E2_];
__device__ __align__(256) __half g_vl[H_*T_*E2_];

// ---------------- helpers ----------------------------------------------------
__device__ __forceinline__ uint32_t smem_to_u32(const void* p) {
    uint32_t a;
    asm("{ .reg .u64 t; cvta.to.shared.u64 t, %1; cvt.u32.u64 %0, t; }" : "=r"(a) : "l"(p));
    return a;
}
#define LDSM4(r, addr) \
    asm volatile("ldmatrix.sync.aligned.m8n8.x4.shared.b16 {%0,%1,%2,%3}, [%4];" \
        : "=r"((r)[0]), "=r"((r)[1]), "=r"((r)[2]), "=r"((r)[3]) : "r"(addr))
#define LDSMT4(r, addr) \
    asm volatile("ldmatrix.sync.aligned.m8n8.x4.trans.shared.b16 {%0,%1,%2,%3}, [%4];" \
        : "=r"((r)[0]), "=r"((r)[1]), "=r"((r)[2]), "=r"((r)[3]) : "r"(addr))
#define MMA16816(c, a, b) \
    asm volatile("mma.sync.aligned.m16n8k16.row.col.f32.f16.f16.f32 " \
        "{%0,%1,%2,%3}, {%4,%5,%6,%7}, {%8,%9}, {%0,%1,%2,%3};" \
        : "+f"((c)[0]), "+f"((c)[1]), "+f"((c)[2]), "+f"((c)[3]) \
        : "r"((a)[0]), "r"((a)[1]), "r"((a)[2]), "r"((a)[3]), "r"((b)[0]), "r"((b)[1]))
#define CP_ASYNC16(sa, ga) \
    asm volatile("cp.async.cg.shared.global [%0], [%1], 16;" :: "r"(sa), "l"(ga))
#define CP_COMMIT() asm volatile("cp.async.commit_group;" ::: "memory")

__device__ __forceinline__ uint32_t packh2(__half a, __half b) {
    __half2 h = __halves2half2(a, b);
    return *(uint32_t*)&h;
}

// ---------------- lambda -----------------------------------------------------
__global__ void lam_kernel(const float* __restrict__ lq1, const float* __restrict__ lq2,
                           const float* __restrict__ lk1, const float* __restrict__ lk2) {
    int h = threadIdx.x;
    if (h < H_) {
        float d1 = 0.f, d2 = 0.f;
        for (int d = 0; d < DK_; d++) {
            d1 += lq1[h*DK_ + d] * lk1[h*DK_ + d];
            d2 += lq2[h*DK_ + d] * lk2[h*DK_ + d];
        }
        g_lam[h] = expf(d1) - expf(d2) + LAMBDA_INIT_;
    }
}

// ---------------- prep: X to fp16 (hi only) ----------------------------------
__global__ void __launch_bounds__(256) split_x(const float* __restrict__ X) {
    int t = blockIdx.x;
    const float* xp = X + (size_t)t * DIM_;
    __half* hp = g_xhi + (size_t)t * DIM_;
    for (int j = threadIdx.x; j < DIM_; j += 256)
        hp[j] = __float2half_rn(xp[j]);
}

// ---------------- prep: transpose + split W ----------------------------------
__global__ void __launch_bounds__(256) transp_w(const float* __restrict__ Wq,
                                                const float* __restrict__ Wk,
                                                const float* __restrict__ Wv) {
    __shared__ float tile[32][33];
    int hs = blockIdx.z;
    int sel = hs >> 4, h = hs & 15;
    const float* W = sel == 0 ? Wq : (sel == 1 ? Wk : Wv);
    int d0 = blockIdx.x * 32;
    int e0 = blockIdx.y * 32;
    int tx = threadIdx.x & 31, ty = threadIdx.x >> 5;
    #pragma unroll
    for (int i = 0; i < 4; i++) {
        int d = d0 + ty + i * 8;
        tile[ty + i * 8][tx] = W[((size_t)h * DIM_ + d) * E2_ + e0 + tx];
    }
    __syncthreads();
    #pragma unroll
    for (int i = 0; i < 4; i++) {
        int e = e0 + ty + i * 8;
        float v = tile[tx][ty + i * 8];
        __half hi = __float2half_rn(v);
        size_t idx = ((size_t)hs * E2_ + e) * DIM_ + d0 + tx;
        g_wthi[idx] = hi;
        g_wtlo[idx] = __float2half_rn(v - __half2float(hi));
    }
}

// ---------------- projection via mma.sync: Xhi*(Whi+Wlo) (round-9 config) ----
#define PRJ_ROWB   144
#define PRJ_TILEB  (128*PRJ_ROWB)        // 18432
#define PRJ_STAGEB (3*PRJ_TILEB)         // 55296
#define PRJ_NSTG   32                    // 2048 / 64

__global__ void __launch_bounds__(256, 2) proj_mma() {
    extern __shared__ char smc[];
    uint32_t sbase = smem_to_u32(smc);
    int tid = threadIdx.x, lane = tid & 31, wid = tid >> 5;
    int tblk = blockIdx.x, h = blockIdx.y, sel = blockIdx.z;
    int row0 = tblk * 128;

    const char* gA0 = (const char*)g_xhi + (size_t)row0 * (DIM_ * 2);
    size_t wofs = (size_t)(sel * H_ + h) * E2_ * (DIM_ * 2);
    const char* gA1 = (const char*)g_wthi + wofs;
    const char* gA2 = (const char*)g_wtlo + wofs;

    int m0 = (wid >> 1) * 32, n0 = (wid & 1) * 64;
    float acc[2][8][4] = {};

    auto issue = [&](int s, int b) {
        uint32_t sb = sbase + b * PRJ_STAGEB;
        size_t k0b = (size_t)s * 128;
        #pragma unroll
        for (int i = 0; i < 4; i++) {
            int l = tid + i * 256;
            int row = l >> 3, seg = l & 7;
            size_t gofs = (size_t)row * (DIM_ * 2) + k0b + seg * 16;
            uint32_t sofs = row * PRJ_ROWB + seg * 16;
            CP_ASYNC16(sb + 0 * PRJ_TILEB + sofs, gA0 + gofs);
            CP_ASYNC16(sb + 1 * PRJ_TILEB + sofs, gA1 + gofs);
            CP_ASYNC16(sb + 2 * PRJ_TILEB + sofs, gA2 + gofs);
        }
        CP_COMMIT();
    };

    issue(0, 0);
    for (int s = 0; s < PRJ_NSTG; s++) {
        int b = s & 1;
        if (s < PRJ_NSTG - 1) issue(s + 1, b ^ 1);
        if (s < PRJ_NSTG - 1) asm volatile("cp.async.wait_group 1;" ::: "memory");
        else                  asm volatile("cp.async.wait_group 0;" ::: "memory");
        __syncthreads();

        uint32_t sA  = sbase + b * PRJ_STAGEB;
        uint32_t sBh = sA + PRJ_TILEB;
        uint32_t sBl = sBh + PRJ_TILEB;
        #pragma unroll
        for (int kk = 0; kk < 64; kk += 16) {
            uint32_t ah[2][4];
            #pragma unroll
            for (int mt = 0; mt < 2; mt++) {
                uint32_t off = (uint32_t)(m0 + mt * 16 + (lane & 15)) * PRJ_ROWB
                             + (kk + (lane >> 4) * 8) * 2;
                LDSM4(ah[mt], sA + off);
            }
            uint32_t bh[4][4], bl[4][4];
            #pragma unroll
            for (int np = 0; np < 4; np++) {
                uint32_t off = (uint32_t)(n0 + np * 16 + (lane & 7) + ((lane >> 4) & 1) * 8) * PRJ_ROWB
                             + (kk + ((lane >> 3) & 1) * 8) * 2;
                LDSM4(bh[np], sBh + off);
                LDSM4(bl[np], sBl + off);
            }
            #pragma unroll
            for (int mt = 0; mt < 2; mt++)
                #pragma unroll
                for (int nt = 0; nt < 8; nt++) {
                    uint32_t* bhp = &bh[nt >> 1][(nt & 1) * 2];
                    uint32_t* blp = &bl[nt >> 1][(nt & 1) * 2];
                    MMA16816(acc[mt][nt], ah[mt], bhp);
                    MMA16816(acc[mt][nt], ah[mt], blp);
                }
        }
        __syncthreads();
    }

    __half* Gh = (sel == 0 ? g_qh : (sel == 1 ? g_kh : g_vh)) + (size_t)h * T_ * E2_;
    __half* Gl = (sel == 0 ? g_ql : (sel == 1 ? g_kl : g_vl)) + (size_t)h * T_ * E2_;
    #pragma unroll
    for (int mt = 0; mt < 2; mt++)
        #pragma unroll
        for (int nt = 0; nt < 8; nt++) {
            int r = row0 + m0 + mt * 16 + (lane >> 2);
            int c = n0 + nt * 8 + (lane & 3) * 2;
            #pragma unroll
            for (int half2i = 0; half2i < 2; half2i++) {
                float v0 = acc[mt][nt][half2i * 2 + 0];
                float v1 = acc[mt][nt][half2i * 2 + 1];
                __half h0 = __float2half_rn(v0), h1 = __float2half_rn(v1);
                __half l0 = __float2half_rn(v0 - __half2float(h0));
                __half l1 = __float2half_rn(v1 - __half2float(h1));
                size_t o = (size_t)(r + half2i * 8) * E2_ + c;
                *(uint32_t*)&Gh[o] = packh2(h0, h1);
                *(uint32_t*)&Gl[o] = packh2(l0, l1);
            }
        }
}

// ---------------- fix-up: 16 state rows with W_s (round-9 config) ------------
__global__ void __launch_bounds__(128) proj_fix(const float* __restrict__ X,
                                                const float* __restrict__ Wqs,
                                                const float* __restrict__ Wks,
                                                const float* __restrict__ Wvs) {
    __shared__ float xs[512][4];
    int h = blockIdx.x;
    int z = blockIdx.y;
    int g = blockIdx.z;
    const float* Ws = z == 0 ? Wqs : (z == 1 ? Wks : Wvs);
    __half* Gh = (z == 0 ? g_qh : (z == 1 ? g_kh : g_vh));
    __half* Gl = (z == 0 ? g_ql : (z == 1 ? g_kl : g_vl));
    int e = threadIdx.x;
    const float* Wp = Ws + (size_t)h * DIM_ * E2_ + e;
    float acc[4] = {};
    for (int d0 = 0; d0 < DIM_; d0 += 512) {
        __syncthreads();
        for (int l = threadIdx.x; l < 4 * 512; l += 128) {
            int ti = l >> 9;
            int c  = l & 511;
            int tok = g * 4 + ti;
            int t  = tok < 8 ? tok : 2032 + tok;
            xs[c][ti] = X[(size_t)t * DIM_ + d0 + c];
        }
        __syncthreads();
        for (int c = 0; c < 512; c++) {
            float w = Wp[(size_t)(d0 + c) * E2_];
            float4 x0 = *(const float4*)&xs[c][0];
            acc[0] = fmaf(x0.x, w, acc[0]);
            acc[1] = fmaf(x0.y, w, acc[1]);
            acc[2] = fmaf(x0.z, w, acc[2]);
            acc[3] = fmaf(x0.w, w, acc[3]);
        }
    }
    #pragma unroll
    for (int ti = 0; ti < 4; ti++) {
        int tok = g * 4 + ti;
        int t = tok < 8 ? tok : 2032 + tok;
        size_t idx = (size_t)h * T_ * E2_ + (size_t)t * E2_ + e;
        float v = acc[ti];
        __half hi = __float2half_rn(v);
        Gh[idx] = hi;
        Gl[idx] = __float2half_rn(v - __half2float(hi));
    }
}

// ---------------- flash attention via mma.sync (round-9 version) -------------
#define AT_ROWB  144
#define AT_VROWB 272
#define AT_QH    0
#define AT_QL    (128*AT_ROWB)
#define AT_ST0   (2*128*AT_ROWB)
#define AT_KH    0
#define AT_KL    (64*AT_ROWB)
#define AT_VH    (2*64*AT_ROWB)
#define AT_VL    (2*64*AT_ROWB + 64*AT_VROWB)
#define AT_STAGE (2*64*AT_ROWB + 2*64*AT_VROWB)
#define AT_SMEM  (AT_ST0 + 2*AT_STAGE)     // 143360

__global__ void __launch_bounds__(256) attn_kernel() {
    extern __shared__ char smc[];
    uint32_t sbase = smem_to_u32(smc);
    int tid = threadIdx.x, lane = tid & 31, wid = tid >> 5;
    int bid = (int)blockIdx.x;
    int qb = 15 - (bid >> 5);
    int rem = bid & 31;
    int h = rem >> 1;
    int which = rem & 1;
    int t0 = qb * 128;

    size_t hbase = (size_t)h * T_ * E2_;
    const char* Qh = (const char*)(g_qh + hbase + (size_t)t0 * E2_ + which * DK_);
    const char* Ql = (const char*)(g_ql + hbase + (size_t)t0 * E2_ + which * DK_);
    const char* Kh = (const char*)(g_kh + hbase + which * DK_);
    const char* Kl = (const char*)(g_kl + hbase + which * DK_);
    const char* Vh = (const char*)(g_vh + hbase);
    const char* Vl = (const char*)(g_vl + hbase);
    float* Ao = (which ? g_att2 : g_att1) + hbase + (size_t)t0 * E2_;

    #pragma unroll
    for (int i = 0; i < 4; i++) {
        int l = tid + i * 256;
        int row = l >> 3, seg = l & 7;
        uint32_t so = row * AT_ROWB + seg * 16;
        size_t go = (size_t)row * 256 + seg * 16;
        CP_ASYNC16(sbase + AT_QH + so, Qh + go);
        CP_ASYNC16(sbase + AT_QL + so, Ql + go);
    }
    CP_COMMIT();

    auto issue_kv = [&](int kb, int b) {
        uint32_t sb = sbase + AT_ST0 + b * AT_STAGE;
        size_t kofs = (size_t)kb * 64 * 256;
        #pragma unroll
        for (int i = 0; i < 2; i++) {
            int l = tid + i * 256;
            int row = l >> 3, seg = l & 7;
            uint32_t so = row * AT_ROWB + seg * 16;
            size_t go = kofs + (size_t)row * 256 + seg * 16;
            CP_ASYNC16(sb + AT_KH + so, Kh + go);
            CP_ASYNC16(sb + AT_KL + so, Kl + go);
        }
        #pragma unroll
        for (int i = 0; i < 4; i++) {
            int l = tid + i * 256;
            int row = l >> 4, seg = l & 15;
            uint32_t so = row * AT_VROWB + seg * 16;
            size_t go = kofs + (size_t)row * 256 + seg * 16;
            CP_ASYNC16(sb + AT_VH + so, Vh + go);
            CP_ASYNC16(sb + AT_VL + so, Vl + go);
        }
        CP_COMMIT();
    };

    issue_kv(0, 0);
    asm volatile("cp.async.wait_group 1;" ::: "memory");
    __syncthreads();

    uint32_t qh[4][4], ql[4][4];
    #pragma unroll
    for (int kt = 0; kt < 4; kt++) {
        uint32_t off = (uint32_t)(wid * 16 + (lane & 15)) * AT_ROWB
                     + (kt * 16 + (lane >> 4) * 8) * 2;
        LDSM4(qh[kt], sbase + AT_QH + off);
        LDSM4(ql[kt], sbase + AT_QL + off);
    }

    float o[16][4] = {};
    float mA = -INFINITY, mB = -INFINITY, lA = 0.f, lB = 0.f;
    int nkb = 2 * qb + 2;

    for (int kb = 0; kb < nkb; kb++) {
        int b = kb & 1;
        if (kb + 1 < nkb) {
            issue_kv(kb + 1, b ^ 1);
            asm volatile("cp.async.wait_group 1;" ::: "memory");
        } else {
            asm volatile("cp.async.wait_group 0;" ::: "memory");
        }
        __syncthreads();

        uint32_t sb = sbase + AT_ST0 + b * AT_STAGE;

        float s[8][4] = {};
        #pragma unroll
        for (int kt = 0; kt < 4; kt++) {
            uint32_t kfh[4][4], kfl[4][4];
            #pragma unroll
            for (int np = 0; np < 4; np++) {
                uint32_t off = (uint32_t)(np * 16 + (lane & 7) + ((lane >> 4) & 1) * 8) * AT_ROWB
                             + (kt * 16 + ((lane >> 3) & 1) * 8) * 2;
                LDSM4(kfh[np], sb + AT_KH + off);
                LDSM4(kfl[np], sb + AT_KL + off);
            }
            #pragma unroll
            for (int nt = 0; nt < 8; nt++) {
                uint32_t* bh = &kfh[nt >> 1][(nt & 1) * 2];
                uint32_t* bl = &kfl[nt >> 1][(nt & 1) * 2];
                MMA16816(s[nt], qh[kt], bh);
                MMA16816(s[nt], ql[kt], bh);
                MMA16816(s[nt], qh[kt], bl);
            }
        }

        bool diag = (kb >= 2 * qb);
        int rA = t0 + wid * 16 + (lane >> 2);
        #pragma unroll
        for (int nt = 0; nt < 8; nt++)
            #pragma unroll
            for (int e = 0; e < 4; e++) {
                float v = s[nt][e] * 0.125f;
                if (diag) {
                    int jc = kb * 64 + nt * 8 + (lane & 3) * 2 + (e & 1);
                    int ir = rA + (e >> 1) * 8;
                    if (jc > ir) v = -1e30f;
                }
                s[nt][e] = v;
            }

        float rmA = -INFINITY, rmB = -INFINITY;
        #pragma unroll
        for (int nt = 0; nt < 8; nt++) {
            rmA = fmaxf(rmA, fmaxf(s[nt][0], s[nt][1]));
            rmB = fmaxf(rmB, fmaxf(s[nt][2], s[nt][3]));
        }
        rmA = fmaxf(rmA, __shfl_xor_sync(0xffffffffu, rmA, 1));
        rmA = fmaxf(rmA, __shfl_xor_sync(0xffffffffu, rmA, 2));
        rmB = fmaxf(rmB, __shfl_xor_sync(0xffffffffu, rmB, 1));
        rmB = fmaxf(rmB, __shfl_xor_sync(0xffffffffu, rmB, 2));
        float nmA = fmaxf(mA, rmA), nmB = fmaxf(mB, rmB);
        float aA = __expf(mA - nmA), aB = __expf(mB - nmB);
        mA = nmA; mB = nmB;
        float rsA = 0.f, rsB = 0.f;
        #pragma unroll
        for (int nt = 0; nt < 8; nt++) {
            s[nt][0] = __expf(s[nt][0] - nmA);
            s[nt][1] = __expf(s[nt][1] - nmA);
            s[nt][2] = __expf(s[nt][2] - nmB);
            s[nt][3] = __expf(s[nt][3] - nmB);
            rsA += s[nt][0] + s[nt][1];
            rsB += s[nt][2] + s[nt][3];
        }
        rsA += __shfl_xor_sync(0xffffffffu, rsA, 1);
        rsA += __shfl_xor_sync(0xffffffffu, rsA, 2);
        rsB += __shfl_xor_sync(0xffffffffu, rsB, 1);
        rsB += __shfl_xor_sync(0xffffffffu, rsB, 2);
        lA = lA * aA + rsA;
        lB = lB * aB + rsB;
        #pragma unroll
        for (int nt = 0; nt < 16; nt++) {
            o[nt][0] *= aA; o[nt][1] *= aA;
            o[nt][2] *= aB; o[nt][3] *= aB;
        }

        uint32_t ph[4][4], pl[4][4];
        #pragma unroll
        for (int kt = 0; kt < 4; kt++)
            #pragma unroll
            for (int half16 = 0; half16 < 2; half16++) {
                float* e = s[2 * kt + half16];
                __half h0 = __float2half_rn(e[0]), h1 = __float2half_rn(e[1]);
                __half h2 = __float2half_rn(e[2]), h3 = __float2half_rn(e[3]);
                ph[kt][half16 * 2 + 0] = packh2(h0, h1);
                ph[kt][half16 * 2 + 1] = packh2(h2, h3);
                pl[kt][half16 * 2 + 0] = packh2(__float2half_rn(e[0] - __half2float(h0)),
                                                __float2half_rn(e[1] - __half2float(h1)));
                pl[kt][half16 * 2 + 1] = packh2(__float2half_rn(e[2] - __half2float(h2)),
                                                __float2half_rn(e[3] - __half2float(h3)));
            }

        #pragma unroll
        for (int kt = 0; kt < 4; kt++) {
            #pragma unroll
            for (int vn = 0; vn < 8; vn++) {
                uint32_t off = (uint32_t)(kt * 16 + (lane & 15)) * AT_VROWB
                             + (vn * 16 + (lane >> 4) * 8) * 2;
                uint32_t vf[4], vg[4];
                LDSMT4(vf, sb + AT_VH + off);
                LDSMT4(vg, sb + AT_VL + off);
                MMA16816(o[2 * vn + 0], ph[kt], &vf[0]);
                MMA16816(o[2 * vn + 0], pl[kt], &vf[0]);
                MMA16816(o[2 * vn + 0], ph[kt], &vg[0]);
                MMA16816(o[2 * vn + 1], ph[kt], &vf[2]);
                MMA16816(o[2 * vn + 1], pl[kt], &vf[2]);
                MMA16816(o[2 * vn + 1], ph[kt], &vg[2]);
            }
        }
        __syncthreads();
    }

    float invA = 1.f / lA, invB = 1.f / lB;
    int rloc = wid * 16 + (lane >> 2);
    #pragma unroll
    for (int nt = 0; nt < 16; nt++) {
        int c = nt * 8 + (lane & 3) * 2;
        *(float2*)&Ao[(size_t)rloc * E2_ + c] = make_float2(o[nt][0] * invA, o[nt][1] * invA);
        *(float2*)&Ao[(size_t)(rloc + 8) * E2_ + c] = make_float2(o[nt][2] * invB, o[nt][3] * invB);
    }
}

// ---------------- combine + layernorm + scale: 4 rows/block, float2 ----------
__global__ void __launch_bounds__(256) final_kernel(const float* __restrict__ gamma,
                                                    const float* __restrict__ beta,
                                                    float* __restrict__ Out) {
    int tid = threadIdx.x;
    int row = blockIdx.x * 4 + (tid >> 6);      // global row 0..32767
    int h = row >> 11;
    int t = row & 2047;
    int le = tid & 63;
    int e = le * 2;
    size_t base = ((size_t)h * T_ + t) * E2_;
    float lam = g_lam[h];
    float2 a1 = *(const float2*)&g_att1[base + e];
    float2 a2 = *(const float2*)&g_att2[base + e];
    float v0 = a1.x - lam * a2.x;
    float v1 = a1.y - lam * a2.y;

    float s1 = v0 + v1;
    float s2 = v0 * v0 + v1 * v1;
    #pragma unroll
    for (int off = 16; off; off >>= 1) {
        s1 += __shfl_xor_sync(0xffffffffu, s1, off);
        s2 += __shfl_xor_sync(0xffffffffu, s2, off);
    }
    __shared__ float red[2][8];
    int w = tid >> 5, lane = tid & 31;
    if (lane == 0) { red[0][w] = s1; red[1][w] = s2; }
    __syncthreads();
    int w0 = (tid >> 6) * 2;                    // this row's warp pair
    float sum = red[0][w0] + red[0][w0 + 1];
    float sq  = red[1][w0] + red[1][w0 + 1];
    float mu  = sum * (1.f / 128.f);
    float var = fmaxf(sq * (1.f / 128.f) - mu * mu, 0.f);
    float rstd = rsqrtf(var + EPS_);
    float2 g = *(const float2*)&gamma[h * E2_ + e];
    float2 bt = *(const float2*)&beta[h * E2_ + e];
    float2 outv;
    outv.x = ((v0 - mu) * rstd * g.x + bt.x) * OUT_SCALE_;
    outv.y = ((v1 - mu) * rstd * g.y + bt.y) * OUT_SCALE_;
    *(float2*)&Out[base + e] = outv;
}

// ---------------- launch -----------------------------------------------------
extern "C" void kernel_launch(void* const* d_in, const int* in_sizes, int n_in,
                              void* d_out, int out_size) {
    const float* x   = (const float*)d_in[0];
    const float* Wq  = (const float*)d_in[1];
    const float* Wk  = (const float*)d_in[2];
    const float* Wv  = (const float*)d_in[3];
    const float* Wqs = (const float*)d_in[4];
    const float* Wks = (const float*)d_in[5];
    const float* Wvs = (const float*)d_in[6];
    const float* lq1 = (const float*)d_in[7];
    const float* lq2 = (const float*)d_in[8];
    const float* lk1 = (const float*)d_in[9];
    const float* lk2 = (const float*)d_in[10];
    const float* gam = (const float*)d_in[11];
    const float* bet = (const float*)d_in[12];
    float* out = (float*)d_out;

    size_t psmem = 2 * PRJ_STAGEB;   // 110592
    cudaFuncSetAttribute(proj_mma, cudaFuncAttributeMaxDynamicSharedMemorySize, (int)psmem);
    cudaFuncSetAttribute(attn_kernel, cudaFuncAttributeMaxDynamicSharedMemorySize, AT_SMEM);

    lam_kernel<<<1, 32>>>(lq1, lq2, lk1, lk2);
    split_x<<<T_, 256>>>(x);
    transp_w<<<dim3(64, 4, 48), 256>>>(Wq, Wk, Wv);
    proj_mma<<<dim3(16, 16, 3), 256, psmem>>>();
    proj_fix<<<dim3(16, 3, 4), 128>>>(x, Wqs, Wks, Wvs);
    attn_kernel<<<512, 256, AT_SMEM>>>();
    final_kernel<<<8192, 256>>>(gam, bet, out);
}

// round 16
// speedup vs baseline: 1.1358x; 1.0493x over previous
#include <cuda_runtime.h>
#include <cuda_fp16.h>
#include <math.h>
#include <cstdint>

#define H_   16
#define T_   2048
#define DIM_ 2048
#define DK_  64
#define E2_  128
#define LAMBDA_INIT_ 0.6192834728526787f
#define OUT_SCALE_   0.3807165271473213f
#define EPS_ 1e-5f

// ---------------- scratch ----------------------------------------------------
__device__ float g_att1[H_*T_*E2_];
__device__ float g_att2[H_*T_*E2_];
__device__ float g_lam[H_];
__device__ __align__(256) __half g_xhi[T_*DIM_];
__device__ __align__(256) __half g_wthi[3*H_*E2_*DIM_];   // [sel][h][e][d]
__device__ __align__(256) __half g_wtlo[3*H_*E2_*DIM_];
__device__ __align__(256) __half g_qh[H_*T_*E2_];
__device__ __align__(256) __half g_ql[H_*T_*E2_];
__device__ __align__(256) __half g_kh[H_*T_*E2_];
__device__ __align__(256) __half g_kl[H_*T_*E2_];
__device__ __align__(256) __half g_vh[H_*T_*E2_];
__device__ __align__(256) __half g_vl[H_*T_*E2_];

// ---------------- helpers ----------------------------------------------------
__device__ __forceinline__ uint32_t smem_to_u32(const void* p) {
    uint32_t a;
    asm("{ .reg .u64 t; cvta.to.shared.u64 t, %1; cvt.u32.u64 %0, t; }" : "=r"(a) : "l"(p));
    return a;
}
#define LDSM4(r, addr) \
    asm volatile("ldmatrix.sync.aligned.m8n8.x4.shared.b16 {%0,%1,%2,%3}, [%4];" \
        : "=r"((r)[0]), "=r"((r)[1]), "=r"((r)[2]), "=r"((r)[3]) : "r"(addr))
#define LDSMT4(r, addr) \
    asm volatile("ldmatrix.sync.aligned.m8n8.x4.trans.shared.b16 {%0,%1,%2,%3}, [%4];" \
        : "=r"((r)[0]), "=r"((r)[1]), "=r"((r)[2]), "=r"((r)[3]) : "r"(addr))
#define MMA16816(c, a, b) \
    asm volatile("mma.sync.aligned.m16n8k16.row.col.f32.f16.f16.f32 " \
        "{%0,%1,%2,%3}, {%4,%5,%6,%7}, {%8,%9}, {%0,%1,%2,%3};" \
        : "+f"((c)[0]), "+f"((c)[1]), "+f"((c)[2]), "+f"((c)[3]) \
        : "r"((a)[0]), "r"((a)[1]), "r"((a)[2]), "r"((a)[3]), "r"((b)[0]), "r"((b)[1]))
#define CP_ASYNC16(sa, ga) \
    asm volatile("cp.async.cg.shared.global [%0], [%1], 16;" :: "r"(sa), "l"(ga))
#define CP_COMMIT() asm volatile("cp.async.commit_group;" ::: "memory")

__device__ __forceinline__ uint32_t packh2(__half a, __half b) {
    __half2 h = __halves2half2(a, b);
    return *(uint32_t*)&h;
}

// ---------------- lambda -----------------------------------------------------
__global__ void lam_kernel(const float* __restrict__ lq1, const float* __restrict__ lq2,
                           const float* __restrict__ lk1, const float* __restrict__ lk2) {
    int h = threadIdx.x;
    if (h < H_) {
        float d1 = 0.f, d2 = 0.f;
        for (int d = 0; d < DK_; d++) {
            d1 += lq1[h*DK_ + d] * lk1[h*DK_ + d];
            d2 += lq2[h*DK_ + d] * lk2[h*DK_ + d];
        }
        g_lam[h] = expf(d1) - expf(d2) + LAMBDA_INIT_;
    }
}

// ---------------- prep: X to fp16 (hi only) ----------------------------------
__global__ void __launch_bounds__(256) split_x(const float* __restrict__ X) {
    int t = blockIdx.x;
    const float* xp = X + (size_t)t * DIM_;
    __half* hp = g_xhi + (size_t)t * DIM_;
    for (int j = threadIdx.x; j < DIM_; j += 256)
        hp[j] = __float2half_rn(xp[j]);
}

// ---------------- prep: transpose + split W ----------------------------------
__global__ void __launch_bounds__(256) transp_w(const float* __restrict__ Wq,
                                                const float* __restrict__ Wk,
                                                const float* __restrict__ Wv) {
    __shared__ float tile[32][33];
    int hs = blockIdx.z;
    int sel = hs >> 4, h = hs & 15;
    const float* W = sel == 0 ? Wq : (sel == 1 ? Wk : Wv);
    int d0 = blockIdx.x * 32;
    int e0 = blockIdx.y * 32;
    int tx = threadIdx.x & 31, ty = threadIdx.x >> 5;
    #pragma unroll
    for (int i = 0; i < 4; i++) {
        int d = d0 + ty + i * 8;
        tile[ty + i * 8][tx] = W[((size_t)h * DIM_ + d) * E2_ + e0 + tx];
    }
    __syncthreads();
    #pragma unroll
    for (int i = 0; i < 4; i++) {
        int e = e0 + ty + i * 8;
        float v = tile[tx][ty + i * 8];
        __half hi = __float2half_rn(v);
        size_t idx = ((size_t)hs * E2_ + e) * DIM_ + d0 + tx;
        g_wthi[idx] = hi;
        g_wtlo[idx] = __float2half_rn(v - __half2float(hi));
    }
}

// ---------------- projection via mma.sync: Xhi*(Whi+Wlo) (round-9 config) ----
#define PRJ_ROWB   144
#define PRJ_TILEB  (128*PRJ_ROWB)        // 18432
#define PRJ_STAGEB (3*PRJ_TILEB)         // 55296
#define PRJ_NSTG   32                    // 2048 / 64

__global__ void __launch_bounds__(256, 2) proj_mma() {
    extern __shared__ char smc[];
    uint32_t sbase = smem_to_u32(smc);
    int tid = threadIdx.x, lane = tid & 31, wid = tid >> 5;
    int tblk = blockIdx.x, h = blockIdx.y, sel = blockIdx.z;
    int row0 = tblk * 128;

    const char* gA0 = (const char*)g_xhi + (size_t)row0 * (DIM_ * 2);
    size_t wofs = (size_t)(sel * H_ + h) * E2_ * (DIM_ * 2);
    const char* gA1 = (const char*)g_wthi + wofs;
    const char* gA2 = (const char*)g_wtlo + wofs;

    int m0 = (wid >> 1) * 32, n0 = (wid & 1) * 64;
    float acc[2][8][4] = {};

    auto issue = [&](int s, int b) {
        uint32_t sb = sbase + b * PRJ_STAGEB;
        size_t k0b = (size_t)s * 128;
        #pragma unroll
        for (int i = 0; i < 4; i++) {
            int l = tid + i * 256;
            int row = l >> 3, seg = l & 7;
            size_t gofs = (size_t)row * (DIM_ * 2) + k0b + seg * 16;
            uint32_t sofs = row * PRJ_ROWB + seg * 16;
            CP_ASYNC16(sb + 0 * PRJ_TILEB + sofs, gA0 + gofs);
            CP_ASYNC16(sb + 1 * PRJ_TILEB + sofs, gA1 + gofs);
            CP_ASYNC16(sb + 2 * PRJ_TILEB + sofs, gA2 + gofs);
        }
        CP_COMMIT();
    };

    issue(0, 0);
    for (int s = 0; s < PRJ_NSTG; s++) {
        int b = s & 1;
        if (s < PRJ_NSTG - 1) issue(s + 1, b ^ 1);
        if (s < PRJ_NSTG - 1) asm volatile("cp.async.wait_group 1;" ::: "memory");
        else                  asm volatile("cp.async.wait_group 0;" ::: "memory");
        __syncthreads();

        uint32_t sA  = sbase + b * PRJ_STAGEB;
        uint32_t sBh = sA + PRJ_TILEB;
        uint32_t sBl = sBh + PRJ_TILEB;
        #pragma unroll
        for (int kk = 0; kk < 64; kk += 16) {
            uint32_t ah[2][4];
            #pragma unroll
            for (int mt = 0; mt < 2; mt++) {
                uint32_t off = (uint32_t)(m0 + mt * 16 + (lane & 15)) * PRJ_ROWB
                             + (kk + (lane >> 4) * 8) * 2;
                LDSM4(ah[mt], sA + off);
            }
            uint32_t bh[4][4], bl[4][4];
            #pragma unroll
            for (int np = 0; np < 4; np++) {
                uint32_t off = (uint32_t)(n0 + np * 16 + (lane & 7) + ((lane >> 4) & 1) * 8) * PRJ_ROWB
                             + (kk + ((lane >> 3) & 1) * 8) * 2;
                LDSM4(bh[np], sBh + off);
                LDSM4(bl[np], sBl + off);
            }
            #pragma unroll
            for (int mt = 0; mt < 2; mt++)
                #pragma unroll
                for (int nt = 0; nt < 8; nt++) {
                    uint32_t* bhp = &bh[nt >> 1][(nt & 1) * 2];
                    uint32_t* blp = &bl[nt >> 1][(nt & 1) * 2];
                    MMA16816(acc[mt][nt], ah[mt], bhp);
                    MMA16816(acc[mt][nt], ah[mt], blp);
                }
        }
        __syncthreads();
    }

    __half* Gh = (sel == 0 ? g_qh : (sel == 1 ? g_kh : g_vh)) + (size_t)h * T_ * E2_;
    __half* Gl = (sel == 0 ? g_ql : (sel == 1 ? g_kl : g_vl)) + (size_t)h * T_ * E2_;
    #pragma unroll
    for (int mt = 0; mt < 2; mt++)
        #pragma unroll
        for (int nt = 0; nt < 8; nt++) {
            int r = row0 + m0 + mt * 16 + (lane >> 2);
            int c = n0 + nt * 8 + (lane & 3) * 2;
            #pragma unroll
            for (int half2i = 0; half2i < 2; half2i++) {
                float v0 = acc[mt][nt][half2i * 2 + 0];
                float v1 = acc[mt][nt][half2i * 2 + 1];
                __half h0 = __float2half_rn(v0), h1 = __float2half_rn(v1);
                __half l0 = __float2half_rn(v0 - __half2float(h0));
                __half l1 = __float2half_rn(v1 - __half2float(h1));
                size_t o = (size_t)(r + half2i * 8) * E2_ + c;
                *(uint32_t*)&Gh[o] = packh2(h0, h1);
                *(uint32_t*)&Gl[o] = packh2(l0, l1);
            }
        }
}

// ---------------- fix-up: 16 state rows with W_s (round-9 config) ------------
__global__ void __launch_bounds__(128) proj_fix(const float* __restrict__ X,
                                                const float* __restrict__ Wqs,
                                                const float* __restrict__ Wks,
                                                const float* __restrict__ Wvs) {
    __shared__ float xs[512][4];
    int h = blockIdx.x;
    int z = blockIdx.y;
    int g = blockIdx.z;
    const float* Ws = z == 0 ? Wqs : (z == 1 ? Wks : Wvs);
    __half* Gh = (z == 0 ? g_qh : (z == 1 ? g_kh : g_vh));
    __half* Gl = (z == 0 ? g_ql : (z == 1 ? g_kl : g_vl));
    int e = threadIdx.x;
    const float* Wp = Ws + (size_t)h * DIM_ * E2_ + e;
    float acc[4] = {};
    for (int d0 = 0; d0 < DIM_; d0 += 512) {
        __syncthreads();
        for (int l = threadIdx.x; l < 4 * 512; l += 128) {
            int ti = l >> 9;
            int c  = l & 511;
            int tok = g * 4 + ti;
            int t  = tok < 8 ? tok : 2032 + tok;
            xs[c][ti] = X[(size_t)t * DIM_ + d0 + c];
        }
        __syncthreads();
        for (int c = 0; c < 512; c++) {
            float w = Wp[(size_t)(d0 + c) * E2_];
            float4 x0 = *(const float4*)&xs[c][0];
            acc[0] = fmaf(x0.x, w, acc[0]);
            acc[1] = fmaf(x0.y, w, acc[1]);
            acc[2] = fmaf(x0.z, w, acc[2]);
            acc[3] = fmaf(x0.w, w, acc[3]);
        }
    }
    #pragma unroll
    for (int ti = 0; ti < 4; ti++) {
        int tok = g * 4 + ti;
        int t = tok < 8 ? tok : 2032 + tok;
        size_t idx = (size_t)h * T_ * E2_ + (size_t)t * E2_ + e;
        float v = acc[ti];
        __half hi = __float2half_rn(v);
        Gh[idx] = hi;
        Gl[idx] = __float2half_rn(v - __half2float(hi));
    }
}

// ---------------- flash attention via mma.sync (no K-lo term) ----------------
// S = (Qh+Ql)*Kh ; PV = (Ph+Pl)*Vh + Ph*Vl
#define AT_ROWB  144
#define AT_VROWB 272
#define AT_QH    0
#define AT_QL    (128*AT_ROWB)
#define AT_ST0   (2*128*AT_ROWB)               // 36864
#define AT_KH    0
#define AT_VH    (64*AT_ROWB)                  // 9216
#define AT_VL    (64*AT_ROWB + 64*AT_VROWB)    // 26624
#define AT_STAGE (64*AT_ROWB + 2*64*AT_VROWB)  // 44032
#define AT_SMEM  (AT_ST0 + 2*AT_STAGE)         // 124928

__global__ void __launch_bounds__(256) attn_kernel() {
    extern __shared__ char smc[];
    uint32_t sbase = smem_to_u32(smc);
    int tid = threadIdx.x, lane = tid & 31, wid = tid >> 5;
    int bid = (int)blockIdx.x;
    int qb = 15 - (bid >> 5);
    int rem = bid & 31;
    int h = rem >> 1;
    int which = rem & 1;
    int t0 = qb * 128;

    size_t hbase = (size_t)h * T_ * E2_;
    const char* Qh = (const char*)(g_qh + hbase + (size_t)t0 * E2_ + which * DK_);
    const char* Ql = (const char*)(g_ql + hbase + (size_t)t0 * E2_ + which * DK_);
    const char* Kh = (const char*)(g_kh + hbase + which * DK_);
    const char* Vh = (const char*)(g_vh + hbase);
    const char* Vl = (const char*)(g_vl + hbase);
    float* Ao = (which ? g_att2 : g_att1) + hbase + (size_t)t0 * E2_;

    #pragma unroll
    for (int i = 0; i < 4; i++) {
        int l = tid + i * 256;
        int row = l >> 3, seg = l & 7;
        uint32_t so = row * AT_ROWB + seg * 16;
        size_t go = (size_t)row * 256 + seg * 16;
        CP_ASYNC16(sbase + AT_QH + so, Qh + go);
        CP_ASYNC16(sbase + AT_QL + so, Ql + go);
    }
    CP_COMMIT();

    auto issue_kv = [&](int kb, int b) {
        uint32_t sb = sbase + AT_ST0 + b * AT_STAGE;
        size_t kofs = (size_t)kb * 64 * 256;
        #pragma unroll
        for (int i = 0; i < 2; i++) {
            int l = tid + i * 256;
            int row = l >> 3, seg = l & 7;
            uint32_t so = row * AT_ROWB + seg * 16;
            size_t go = kofs + (size_t)row * 256 + seg * 16;
            CP_ASYNC16(sb + AT_KH + so, Kh + go);
        }
        #pragma unroll
        for (int i = 0; i < 4; i++) {
            int l = tid + i * 256;
            int row = l >> 4, seg = l & 15;
            uint32_t so = row * AT_VROWB + seg * 16;
            size_t go = kofs + (size_t)row * 256 + seg * 16;
            CP_ASYNC16(sb + AT_VH + so, Vh + go);
            CP_ASYNC16(sb + AT_VL + so, Vl + go);
        }
        CP_COMMIT();
    };

    issue_kv(0, 0);
    asm volatile("cp.async.wait_group 1;" ::: "memory");
    __syncthreads();

    uint32_t qh[4][4], ql[4][4];
    #pragma unroll
    for (int kt = 0; kt < 4; kt++) {
        uint32_t off = (uint32_t)(wid * 16 + (lane & 15)) * AT_ROWB
                     + (kt * 16 + (lane >> 4) * 8) * 2;
        LDSM4(qh[kt], sbase + AT_QH + off);
        LDSM4(ql[kt], sbase + AT_QL + off);
    }

    float o[16][4] = {};
    float mA = -INFINITY, mB = -INFINITY, lA = 0.f, lB = 0.f;
    int nkb = 2 * qb + 2;

    for (int kb = 0; kb < nkb; kb++) {
        int b = kb & 1;
        if (kb + 1 < nkb) {
            issue_kv(kb + 1, b ^ 1);
            asm volatile("cp.async.wait_group 1;" ::: "memory");
        } else {
            asm volatile("cp.async.wait_group 0;" ::: "memory");
        }
        __syncthreads();

        uint32_t sb = sbase + AT_ST0 + b * AT_STAGE;

        // ---- S = (Qh+Ql) Kh ----
        float s[8][4] = {};
        #pragma unroll
        for (int kt = 0; kt < 4; kt++) {
            uint32_t kfh[4][4];
            #pragma unroll
            for (int np = 0; np < 4; np++) {
                uint32_t off = (uint32_t)(np * 16 + (lane & 7) + ((lane >> 4) & 1) * 8) * AT_ROWB
                             + (kt * 16 + ((lane >> 3) & 1) * 8) * 2;
                LDSM4(kfh[np], sb + AT_KH + off);
            }
            #pragma unroll
            for (int nt = 0; nt < 8; nt++) {
                uint32_t* bh = &kfh[nt >> 1][(nt & 1) * 2];
                MMA16816(s[nt], qh[kt], bh);
                MMA16816(s[nt], ql[kt], bh);
            }
        }

        bool diag = (kb >= 2 * qb);
        int rA = t0 + wid * 16 + (lane >> 2);
        #pragma unroll
        for (int nt = 0; nt < 8; nt++)
            #pragma unroll
            for (int e = 0; e < 4; e++) {
                float v = s[nt][e] * 0.125f;
                if (diag) {
                    int jc = kb * 64 + nt * 8 + (lane & 3) * 2 + (e & 1);
                    int ir = rA + (e >> 1) * 8;
                    if (jc > ir) v = -1e30f;
                }
                s[nt][e] = v;
            }

        float rmA = -INFINITY, rmB = -INFINITY;
        #pragma unroll
        for (int nt = 0; nt < 8; nt++) {
            rmA = fmaxf(rmA, fmaxf(s[nt][0], s[nt][1]));
            rmB = fmaxf(rmB, fmaxf(s[nt][2], s[nt][3]));
        }
        rmA = fmaxf(rmA, __shfl_xor_sync(0xffffffffu, rmA, 1));
        rmA = fmaxf(rmA, __shfl_xor_sync(0xffffffffu, rmA, 2));
        rmB = fmaxf(rmB, __shfl_xor_sync(0xffffffffu, rmB, 1));
        rmB = fmaxf(rmB, __shfl_xor_sync(0xffffffffu, rmB, 2));
        float nmA = fmaxf(mA, rmA), nmB = fmaxf(mB, rmB);
        float aA = __expf(mA - nmA), aB = __expf(mB - nmB);
        mA = nmA; mB = nmB;
        float rsA = 0.f, rsB = 0.f;
        #pragma unroll
        for (int nt = 0; nt < 8; nt++) {
            s[nt][0] = __expf(s[nt][0] - nmA);
            s[nt][1] = __expf(s[nt][1] - nmA);
            s[nt][2] = __expf(s[nt][2] - nmB);
            s[nt][3] = __expf(s[nt][3] - nmB);
            rsA += s[nt][0] + s[nt][1];
            rsB += s[nt][2] + s[nt][3];
        }
        rsA += __shfl_xor_sync(0xffffffffu, rsA, 1);
        rsA += __shfl_xor_sync(0xffffffffu, rsA, 2);
        rsB += __shfl_xor_sync(0xffffffffu, rsB, 1);
        rsB += __shfl_xor_sync(0xffffffffu, rsB, 2);
        lA = lA * aA + rsA;
        lB = lB * aB + rsB;
        #pragma unroll
        for (int nt = 0; nt < 16; nt++) {
            o[nt][0] *= aA; o[nt][1] *= aA;
            o[nt][2] *= aB; o[nt][3] *= aB;
        }

        uint32_t ph[4][4], pl[4][4];
        #pragma unroll
        for (int kt = 0; kt < 4; kt++)
            #pragma unroll
            for (int half16 = 0; half16 < 2; half16++) {
                float* e = s[2 * kt + half16];
                __half h0 = __float2half_rn(e[0]), h1 = __float2half_rn(e[1]);
                __half h2 = __float2half_rn(e[2]), h3 = __float2half_rn(e[3]);
                ph[kt][half16 * 2 + 0] = packh2(h0, h1);
                ph[kt][half16 * 2 + 1] = packh2(h2, h3);
                pl[kt][half16 * 2 + 0] = packh2(__float2half_rn(e[0] - __half2float(h0)),
                                                __float2half_rn(e[1] - __half2float(h1)));
                pl[kt][half16 * 2 + 1] = packh2(__float2half_rn(e[2] - __half2float(h2)),
                                                __float2half_rn(e[3] - __half2float(h3)));
            }

        #pragma unroll
        for (int kt = 0; kt < 4; kt++) {
            #pragma unroll
            for (int vn = 0; vn < 8; vn++) {
                uint32_t off = (uint32_t)(kt * 16 + (lane & 15)) * AT_VROWB
                             + (vn * 16 + (lane >> 4) * 8) * 2;
                uint32_t vf[4], vg[4];
                LDSMT4(vf, sb + AT_VH + off);
                LDSMT4(vg, sb + AT_VL + off);
                MMA16816(o[2 * vn + 0], ph[kt], &vf[0]);
                MMA16816(o[2 * vn + 0], pl[kt], &vf[0]);
                MMA16816(o[2 * vn + 0], ph[kt], &vg[0]);
                MMA16816(o[2 * vn + 1], ph[kt], &vf[2]);
                MMA16816(o[2 * vn + 1], pl[kt], &vf[2]);
                MMA16816(o[2 * vn + 1], ph[kt], &vg[2]);
            }
        }
        __syncthreads();
    }

    float invA = 1.f / lA, invB = 1.f / lB;
    int rloc = wid * 16 + (lane >> 2);
    #pragma unroll
    for (int nt = 0; nt < 16; nt++) {
        int c = nt * 8 + (lane & 3) * 2;
        *(float2*)&Ao[(size_t)rloc * E2_ + c] = make_float2(o[nt][0] * invA, o[nt][1] * invA);
        *(float2*)&Ao[(size_t)(rloc + 8) * E2_ + c] = make_float2(o[nt][2] * invB, o[nt][3] * invB);
    }
}

// ---------------- combine + layernorm + scale: 4 rows/block, float2 ----------
__global__ void __launch_bounds__(256) final_kernel(const float* __restrict__ gamma,
                                                    const float* __restrict__ beta,
                                                    float* __restrict__ Out) {
    int tid = threadIdx.x;
    int row = blockIdx.x * 4 + (tid >> 6);
    int h = row >> 11;
    int t = row & 2047;
    int le = tid & 63;
    int e = le * 2;
    size_t base = ((size_t)h * T_ + t) * E2_;
    float lam = g_lam[h];
    float2 a1 = *(const float2*)&g_att1[base + e];
    float2 a2 = *(const float2*)&g_att2[base + e];
    float v0 = a1.x - lam * a2.x;
    float v1 = a1.y - lam * a2.y;

    float s1 = v0 + v1;
    float s2 = v0 * v0 + v1 * v1;
    #pragma unroll
    for (int off = 16; off; off >>= 1) {
        s1 += __shfl_xor_sync(0xffffffffu, s1, off);
        s2 += __shfl_xor_sync(0xffffffffu, s2, off);
    }
    __shared__ float red[2][8];
    int w = tid >> 5, lane = tid & 31;
    if (lane == 0) { red[0][w] = s1; red[1][w] = s2; }
    __syncthreads();
    int w0 = (tid >> 6) * 2;
    float sum = red[0][w0] + red[0][w0 + 1];
    float sq  = red[1][w0] + red[1][w0 + 1];
    float mu  = sum * (1.f / 128.f);
    float var = fmaxf(sq * (1.f / 128.f) - mu * mu, 0.f);
    float rstd = rsqrtf(var + EPS_);
    float2 g = *(const float2*)&gamma[h * E2_ + e];
    float2 bt = *(const float2*)&beta[h * E2_ + e];
    float2 outv;
    outv.x = ((v0 - mu) * rstd * g.x + bt.x) * OUT_SCALE_;
    outv.y = ((v1 - mu) * rstd * g.y + bt.y) * OUT_SCALE_;
    *(float2*)&Out[base + e] = outv;
}

// ---------------- launch -----------------------------------------------------
extern "C" void kernel_launch(void* const* d_in, const int* in_sizes, int n_in,
                              void* d_out, int out_size) {
    const float* x   = (const float*)d_in[0];
    const float* Wq  = (const float*)d_in[1];
    const float* Wk  = (const float*)d_in[2];
    const float* Wv  = (const float*)d_in[3];
    const float* Wqs = (const float*)d_in[4];
    const float* Wks = (const float*)d_in[5];
    const float* Wvs = (const float*)d_in[6];
    const float* lq1 = (const float*)d_in[7];
    const float* lq2 = (const float*)d_in[8];
    const float* lk1 = (const float*)d_in[9];
    const float* lk2 = (const float*)d_in[10];
    const float* gam = (const float*)d_in[11];
    const float* bet = (const float*)d_in[12];
    float* out = (float*)d_out;

    size_t psmem = 2 * PRJ_STAGEB;   // 110592
    cudaFuncSetAttribute(proj_mma, cudaFuncAttributeMaxDynamicSharedMemorySize, (int)psmem);
    cudaFuncSetAttribute(attn_kernel, cudaFuncAttributeMaxDynamicSharedMemorySize, AT_SMEM);

    lam_kernel<<<1, 32>>>(lq1, lq2, lk1, lk2);
    split_x<<<T_, 256>>>(x);
    transp_w<<<dim3(64, 4, 48), 256>>>(Wq, Wk, Wv);
    proj_mma<<<dim3(16, 16, 3), 256, psmem>>>();
    proj_fix<<<dim3(16, 3, 4), 128>>>(x, Wqs, Wks, Wvs);
    attn_kernel<<<512, 256, AT_SMEM>>>();
    final_kernel<<<8192, 256>>>(gam, bet, out);
}

// round 17
// speedup vs baseline: 1.2021x; 1.0584x over previous
#include <cuda_runtime.h>
#include <cuda_fp16.h>
#include <math.h>
#include <cstdint>

#define H_   16
#define T_   2048
#define DIM_ 2048
#define DK_  64
#define E2_  128
#define LAMBDA_INIT_ 0.6192834728526787f
#define OUT_SCALE_   0.3807165271473213f
#define EPS_ 1e-5f

// ---------------- scratch ----------------------------------------------------
__device__ float g_att1[H_*T_*E2_];
__device__ float g_att2[H_*T_*E2_];
__device__ float g_lam[H_];
__device__ __align__(256) __half g_xhi[T_*DIM_];
__device__ __align__(256) __half g_wthi[3*H_*E2_*DIM_];   // [sel][h][e][d]
__device__ __align__(256) __half g_wtlo[3*H_*E2_*DIM_];
__device__ __align__(256) __half g_qh[H_*T_*E2_];
__device__ __align__(256) __half g_ql[H_*T_*E2_];
__device__ __align__(256) __half g_kh[H_*T_*E2_];
__device__ __align__(256) __half g_kl[H_*T_*E2_];
__device__ __align__(256) __half g_vh[H_*T_*E2_];
__device__ __align__(256) __half g_vl[H_*T_*E2_];

// ---------------- helpers ----------------------------------------------------
__device__ __forceinline__ uint32_t smem_to_u32(const void* p) {
    uint32_t a;
    asm("{ .reg .u64 t; cvta.to.shared.u64 t, %1; cvt.u32.u64 %0, t; }" : "=r"(a) : "l"(p));
    return a;
}
#define LDSM4(r, addr) \
    asm volatile("ldmatrix.sync.aligned.m8n8.x4.shared.b16 {%0,%1,%2,%3}, [%4];" \
        : "=r"((r)[0]), "=r"((r)[1]), "=r"((r)[2]), "=r"((r)[3]) : "r"(addr))
#define LDSMT4(r, addr) \
    asm volatile("ldmatrix.sync.aligned.m8n8.x4.trans.shared.b16 {%0,%1,%2,%3}, [%4];" \
        : "=r"((r)[0]), "=r"((r)[1]), "=r"((r)[2]), "=r"((r)[3]) : "r"(addr))
#define MMA16816(c, a, b) \
    asm volatile("mma.sync.aligned.m16n8k16.row.col.f32.f16.f16.f32 " \
        "{%0,%1,%2,%3}, {%4,%5,%6,%7}, {%8,%9}, {%0,%1,%2,%3};" \
        : "+f"((c)[0]), "+f"((c)[1]), "+f"((c)[2]), "+f"((c)[3]) \
        : "r"((a)[0]), "r"((a)[1]), "r"((a)[2]), "r"((a)[3]), "r"((b)[0]), "r"((b)[1]))
#define CP_ASYNC16(sa, ga) \
    asm volatile("cp.async.cg.shared.global [%0], [%1], 16;" :: "r"(sa), "l"(ga))
#define CP_COMMIT() asm volatile("cp.async.commit_group;" ::: "memory")

__device__ __forceinline__ uint32_t packh2(__half a, __half b) {
    __half2 h = __halves2half2(a, b);
    return *(uint32_t*)&h;
}

// ---------------- lambda -----------------------------------------------------
__global__ void lam_kernel(const float* __restrict__ lq1, const float* __restrict__ lq2,
                           const float* __restrict__ lk1, const float* __restrict__ lk2) {
    int h = threadIdx.x;
    if (h < H_) {
        float d1 = 0.f, d2 = 0.f;
        for (int d = 0; d < DK_; d++) {
            d1 += lq1[h*DK_ + d] * lk1[h*DK_ + d];
            d2 += lq2[h*DK_ + d] * lk2[h*DK_ + d];
        }
        g_lam[h] = expf(d1) - expf(d2) + LAMBDA_INIT_;
    }
}

// ---------------- prep: X to fp16 (hi only) ----------------------------------
__global__ void __launch_bounds__(256) split_x(const float* __restrict__ X) {
    int t = blockIdx.x;
    const float* xp = X + (size_t)t * DIM_;
    __half* hp = g_xhi + (size_t)t * DIM_;
    for (int j = threadIdx.x; j < DIM_; j += 256)
        hp[j] = __float2half_rn(xp[j]);
}

// ---------------- prep: transpose + split W ----------------------------------
__global__ void __launch_bounds__(256) transp_w(const float* __restrict__ Wq,
                                                const float* __restrict__ Wk,
                                                const float* __restrict__ Wv) {
    __shared__ float tile[32][33];
    int hs = blockIdx.z;
    int sel = hs >> 4, h = hs & 15;
    const float* W = sel == 0 ? Wq : (sel == 1 ? Wk : Wv);
    int d0 = blockIdx.x * 32;
    int e0 = blockIdx.y * 32;
    int tx = threadIdx.x & 31, ty = threadIdx.x >> 5;
    #pragma unroll
    for (int i = 0; i < 4; i++) {
        int d = d0 + ty + i * 8;
        tile[ty + i * 8][tx] = W[((size_t)h * DIM_ + d) * E2_ + e0 + tx];
    }
    __syncthreads();
    #pragma unroll
    for (int i = 0; i < 4; i++) {
        int e = e0 + ty + i * 8;
        float v = tile[tx][ty + i * 8];
        __half hi = __float2half_rn(v);
        size_t idx = ((size_t)hs * E2_ + e) * DIM_ + d0 + tx;
        g_wthi[idx] = hi;
        g_wtlo[idx] = __float2half_rn(v - __half2float(hi));
    }
}

// ---------------- projection via mma.sync: Xhi*(Whi+Wlo) (round-9 config) ----
#define PRJ_ROWB   144
#define PRJ_TILEB  (128*PRJ_ROWB)        // 18432
#define PRJ_STAGEB (3*PRJ_TILEB)         // 55296
#define PRJ_NSTG   32                    // 2048 / 64

__global__ void __launch_bounds__(256, 2) proj_mma() {
    extern __shared__ char smc[];
    uint32_t sbase = smem_to_u32(smc);
    int tid = threadIdx.x, lane = tid & 31, wid = tid >> 5;
    int tblk = blockIdx.x, h = blockIdx.y, sel = blockIdx.z;
    int row0 = tblk * 128;

    const char* gA0 = (const char*)g_xhi + (size_t)row0 * (DIM_ * 2);
    size_t wofs = (size_t)(sel * H_ + h) * E2_ * (DIM_ * 2);
    const char* gA1 = (const char*)g_wthi + wofs;
    const char* gA2 = (const char*)g_wtlo + wofs;

    int m0 = (wid >> 1) * 32, n0 = (wid & 1) * 64;
    float acc[2][8][4] = {};

    auto issue = [&](int s, int b) {
        uint32_t sb = sbase + b * PRJ_STAGEB;
        size_t k0b = (size_t)s * 128;
        #pragma unroll
        for (int i = 0; i < 4; i++) {
            int l = tid + i * 256;
            int row = l >> 3, seg = l & 7;
            size_t gofs = (size_t)row * (DIM_ * 2) + k0b + seg * 16;
            uint32_t sofs = row * PRJ_ROWB + seg * 16;
            CP_ASYNC16(sb + 0 * PRJ_TILEB + sofs, gA0 + gofs);
            CP_ASYNC16(sb + 1 * PRJ_TILEB + sofs, gA1 + gofs);
            CP_ASYNC16(sb + 2 * PRJ_TILEB + sofs, gA2 + gofs);
        }
        CP_COMMIT();
    };

    issue(0, 0);
    for (int s = 0; s < PRJ_NSTG; s++) {
        int b = s & 1;
        if (s < PRJ_NSTG - 1) issue(s + 1, b ^ 1);
        if (s < PRJ_NSTG - 1) asm volatile("cp.async.wait_group 1;" ::: "memory");
        else                  asm volatile("cp.async.wait_group 0;" ::: "memory");
        __syncthreads();

        uint32_t sA  = sbase + b * PRJ_STAGEB;
        uint32_t sBh = sA + PRJ_TILEB;
        uint32_t sBl = sBh + PRJ_TILEB;
        #pragma unroll
        for (int kk = 0; kk < 64; kk += 16) {
            uint32_t ah[2][4];
            #pragma unroll
            for (int mt = 0; mt < 2; mt++) {
                uint32_t off = (uint32_t)(m0 + mt * 16 + (lane & 15)) * PRJ_ROWB
                             + (kk + (lane >> 4) * 8) * 2;
                LDSM4(ah[mt], sA + off);
            }
            uint32_t bh[4][4], bl[4][4];
            #pragma unroll
            for (int np = 0; np < 4; np++) {
                uint32_t off = (uint32_t)(n0 + np * 16 + (lane & 7) + ((lane >> 4) & 1) * 8) * PRJ_ROWB
                             + (kk + ((lane >> 3) & 1) * 8) * 2;
                LDSM4(bh[np], sBh + off);
                LDSM4(bl[np], sBl + off);
            }
            #pragma unroll
            for (int mt = 0; mt < 2; mt++)
                #pragma unroll
                for (int nt = 0; nt < 8; nt++) {
                    uint32_t* bhp = &bh[nt >> 1][(nt & 1) * 2];
                    uint32_t* blp = &bl[nt >> 1][(nt & 1) * 2];
                    MMA16816(acc[mt][nt], ah[mt], bhp);
                    MMA16816(acc[mt][nt], ah[mt], blp);
                }
        }
        __syncthreads();
    }

    __half* Gh = (sel == 0 ? g_qh : (sel == 1 ? g_kh : g_vh)) + (size_t)h * T_ * E2_;
    __half* Gl = (sel == 0 ? g_ql : (sel == 1 ? g_kl : g_vl)) + (size_t)h * T_ * E2_;
    #pragma unroll
    for (int mt = 0; mt < 2; mt++)
        #pragma unroll
        for (int nt = 0; nt < 8; nt++) {
            int r = row0 + m0 + mt * 16 + (lane >> 2);
            int c = n0 + nt * 8 + (lane & 3) * 2;
            #pragma unroll
            for (int half2i = 0; half2i < 2; half2i++) {
                float v0 = acc[mt][nt][half2i * 2 + 0];
                float v1 = acc[mt][nt][half2i * 2 + 1];
                __half h0 = __float2half_rn(v0), h1 = __float2half_rn(v1);
                __half l0 = __float2half_rn(v0 - __half2float(h0));
                __half l1 = __float2half_rn(v1 - __half2float(h1));
                size_t o = (size_t)(r + half2i * 8) * E2_ + c;
                *(uint32_t*)&Gh[o] = packh2(h0, h1);
                *(uint32_t*)&Gl[o] = packh2(l0, l1);
            }
        }
}

// ---------------- fix-up: 16 state rows with W_s (round-9 config) ------------
__global__ void __launch_bounds__(128) proj_fix(const float* __restrict__ X,
                                                const float* __restrict__ Wqs,
                                                const float* __restrict__ Wks,
                                                const float* __restrict__ Wvs) {
    __shared__ float xs[512][4];
    int h = blockIdx.x;
    int z = blockIdx.y;
    int g = blockIdx.z;
    const float* Ws = z == 0 ? Wqs : (z == 1 ? Wks : Wvs);
    __half* Gh = (z == 0 ? g_qh : (z == 1 ? g_kh : g_vh));
    __half* Gl = (z == 0 ? g_ql : (z == 1 ? g_kl : g_vl));
    int e = threadIdx.x;
    const float* Wp = Ws + (size_t)h * DIM_ * E2_ + e;
    float acc[4] = {};
    for (int d0 = 0; d0 < DIM_; d0 += 512) {
        __syncthreads();
        for (int l = threadIdx.x; l < 4 * 512; l += 128) {
            int ti = l >> 9;
            int c  = l & 511;
            int tok = g * 4 + ti;
            int t  = tok < 8 ? tok : 2032 + tok;
            xs[c][ti] = X[(size_t)t * DIM_ + d0 + c];
        }
        __syncthreads();
        for (int c = 0; c < 512; c++) {
            float w = Wp[(size_t)(d0 + c) * E2_];
            float4 x0 = *(const float4*)&xs[c][0];
            acc[0] = fmaf(x0.x, w, acc[0]);
            acc[1] = fmaf(x0.y, w, acc[1]);
            acc[2] = fmaf(x0.z, w, acc[2]);
            acc[3] = fmaf(x0.w, w, acc[3]);
        }
    }
    #pragma unroll
    for (int ti = 0; ti < 4; ti++) {
        int tok = g * 4 + ti;
        int t = tok < 8 ? tok : 2032 + tok;
        size_t idx = (size_t)h * T_ * E2_ + (size_t)t * E2_ + e;
        float v = acc[ti];
        __half hi = __float2half_rn(v);
        Gh[idx] = hi;
        Gl[idx] = __float2half_rn(v - __half2float(hi));
    }
}

// ---------------- flash attention via mma.sync (no K-lo, no V-lo) ------------
// S = (Qh+Ql)*Kh ; PV = (Ph+Pl)*Vh
#define AT_ROWB  144
#define AT_VROWB 272
#define AT_QH    0
#define AT_QL    (128*AT_ROWB)
#define AT_ST0   (2*128*AT_ROWB)               // 36864
#define AT_KH    0
#define AT_VH    (64*AT_ROWB)                  // 9216
#define AT_STAGE (64*AT_ROWB + 64*AT_VROWB)    // 26624
#define AT_SMEM  (AT_ST0 + 2*AT_STAGE)         // 90112

__global__ void __launch_bounds__(256) attn_kernel() {
    extern __shared__ char smc[];
    uint32_t sbase = smem_to_u32(smc);
    int tid = threadIdx.x, lane = tid & 31, wid = tid >> 5;
    int bid = (int)blockIdx.x;
    int qb = 15 - (bid >> 5);
    int rem = bid & 31;
    int h = rem >> 1;
    int which = rem & 1;
    int t0 = qb * 128;

    size_t hbase = (size_t)h * T_ * E2_;
    const char* Qh = (const char*)(g_qh + hbase + (size_t)t0 * E2_ + which * DK_);
    const char* Ql = (const char*)(g_ql + hbase + (size_t)t0 * E2_ + which * DK_);
    const char* Kh = (const char*)(g_kh + hbase + which * DK_);
    const char* Vh = (const char*)(g_vh + hbase);
    float* Ao = (which ? g_att2 : g_att1) + hbase + (size_t)t0 * E2_;

    #pragma unroll
    for (int i = 0; i < 4; i++) {
        int l = tid + i * 256;
        int row = l >> 3, seg = l & 7;
        uint32_t so = row * AT_ROWB + seg * 16;
        size_t go = (size_t)row * 256 + seg * 16;
        CP_ASYNC16(sbase + AT_QH + so, Qh + go);
        CP_ASYNC16(sbase + AT_QL + so, Ql + go);
    }
    CP_COMMIT();

    auto issue_kv = [&](int kb, int b) {
        uint32_t sb = sbase + AT_ST0 + b * AT_STAGE;
        size_t kofs = (size_t)kb * 64 * 256;
        #pragma unroll
        for (int i = 0; i < 2; i++) {
            int l = tid + i * 256;
            int row = l >> 3, seg = l & 7;
            uint32_t so = row * AT_ROWB + seg * 16;
            size_t go = kofs + (size_t)row * 256 + seg * 16;
            CP_ASYNC16(sb + AT_KH + so, Kh + go);
        }
        #pragma unroll
        for (int i = 0; i < 4; i++) {
            int l = tid + i * 256;
            int row = l >> 4, seg = l & 15;
            uint32_t so = row * AT_VROWB + seg * 16;
            size_t go = kofs + (size_t)row * 256 + seg * 16;
            CP_ASYNC16(sb + AT_VH + so, Vh + go);
        }
        CP_COMMIT();
    };

    issue_kv(0, 0);
    asm volatile("cp.async.wait_group 1;" ::: "memory");
    __syncthreads();

    uint32_t qh[4][4], ql[4][4];
    #pragma unroll
    for (int kt = 0; kt < 4; kt++) {
        uint32_t off = (uint32_t)(wid * 16 + (lane & 15)) * AT_ROWB
                     + (kt * 16 + (lane >> 4) * 8) * 2;
        LDSM4(qh[kt], sbase + AT_QH + off);
        LDSM4(ql[kt], sbase + AT_QL + off);
    }

    float o[16][4] = {};
    float mA = -INFINITY, mB = -INFINITY, lA = 0.f, lB = 0.f;
    int nkb = 2 * qb + 2;

    for (int kb = 0; kb < nkb; kb++) {
        int b = kb & 1;
        if (kb + 1 < nkb) {
            issue_kv(kb + 1, b ^ 1);
            asm volatile("cp.async.wait_group 1;" ::: "memory");
        } else {
            asm volatile("cp.async.wait_group 0;" ::: "memory");
        }
        __syncthreads();

        uint32_t sb = sbase + AT_ST0 + b * AT_STAGE;

        // ---- S = (Qh+Ql) Kh ----
        float s[8][4] = {};
        #pragma unroll
        for (int kt = 0; kt < 4; kt++) {
            uint32_t kfh[4][4];
            #pragma unroll
            for (int np = 0; np < 4; np++) {
                uint32_t off = (uint32_t)(np * 16 + (lane & 7) + ((lane >> 4) & 1) * 8) * AT_ROWB
                             + (kt * 16 + ((lane >> 3) & 1) * 8) * 2;
                LDSM4(kfh[np], sb + AT_KH + off);
            }
            #pragma unroll
            for (int nt = 0; nt < 8; nt++) {
                uint32_t* bh = &kfh[nt >> 1][(nt & 1) * 2];
                MMA16816(s[nt], qh[kt], bh);
                MMA16816(s[nt], ql[kt], bh);
            }
        }

        bool diag = (kb >= 2 * qb);
        int rA = t0 + wid * 16 + (lane >> 2);
        #pragma unroll
        for (int nt = 0; nt < 8; nt++)
            #pragma unroll
            for (int e = 0; e < 4; e++) {
                float v = s[nt][e] * 0.125f;
                if (diag) {
                    int jc = kb * 64 + nt * 8 + (lane & 3) * 2 + (e & 1);
                    int ir = rA + (e >> 1) * 8;
                    if (jc > ir) v = -1e30f;
                }
                s[nt][e] = v;
            }

        float rmA = -INFINITY, rmB = -INFINITY;
        #pragma unroll
        for (int nt = 0; nt < 8; nt++) {
            rmA = fmaxf(rmA, fmaxf(s[nt][0], s[nt][1]));
            rmB = fmaxf(rmB, fmaxf(s[nt][2], s[nt][3]));
        }
        rmA = fmaxf(rmA, __shfl_xor_sync(0xffffffffu, rmA, 1));
        rmA = fmaxf(rmA, __shfl_xor_sync(0xffffffffu, rmA, 2));
        rmB = fmaxf(rmB, __shfl_xor_sync(0xffffffffu, rmB, 1));
        rmB = fmaxf(rmB, __shfl_xor_sync(0xffffffffu, rmB, 2));
        float nmA = fmaxf(mA, rmA), nmB = fmaxf(mB, rmB);
        float aA = __expf(mA - nmA), aB = __expf(mB - nmB);
        mA = nmA; mB = nmB;
        float rsA = 0.f, rsB = 0.f;
        #pragma unroll
        for (int nt = 0; nt < 8; nt++) {
            s[nt][0] = __expf(s[nt][0] - nmA);
            s[nt][1] = __expf(s[nt][1] - nmA);
            s[nt][2] = __expf(s[nt][2] - nmB);
            s[nt][3] = __expf(s[nt][3] - nmB);
            rsA += s[nt][0] + s[nt][1];
            rsB += s[nt][2] + s[nt][3];
        }
        rsA += __shfl_xor_sync(0xffffffffu, rsA, 1);
        rsA += __shfl_xor_sync(0xffffffffu, rsA, 2);
        rsB += __shfl_xor_sync(0xffffffffu, rsB, 1);
        rsB += __shfl_xor_sync(0xffffffffu, rsB, 2);
        lA = lA * aA + rsA;
        lB = lB * aB + rsB;
        #pragma unroll
        for (int nt = 0; nt < 16; nt++) {
            o[nt][0] *= aA; o[nt][1] *= aA;
            o[nt][2] *= aB; o[nt][3] *= aB;
        }

        uint32_t ph[4][4], pl[4][4];
        #pragma unroll
        for (int kt = 0; kt < 4; kt++)
            #pragma unroll
            for (int half16 = 0; half16 < 2; half16++) {
                float* e = s[2 * kt + half16];
                __half h0 = __float2half_rn(e[0]), h1 = __float2half_rn(e[1]);
                __half h2 = __float2half_rn(e[2]), h3 = __float2half_rn(e[3]);
                ph[kt][half16 * 2 + 0] = packh2(h0, h1);
                ph[kt][half16 * 2 + 1] = packh2(h2, h3);
                pl[kt][half16 * 2 + 0] = packh2(__float2half_rn(e[0] - __half2float(h0)),
                                                __float2half_rn(e[1] - __half2float(h1)));
                pl[kt][half16 * 2 + 1] = packh2(__float2half_rn(e[2] - __half2float(h2)),
                                                __float2half_rn(e[3] - __half2float(h3)));
            }

        // ---- O += (Ph+Pl) Vh ----
        #pragma unroll
        for (int kt = 0; kt < 4; kt++) {
            #pragma unroll
            for (int vn = 0; vn < 8; vn++) {
                uint32_t off = (uint32_t)(kt * 16 + (lane & 15)) * AT_VROWB
                             + (vn * 16 + (lane >> 4) * 8) * 2;
                uint32_t vf[4];
                LDSMT4(vf, sb + AT_VH + off);
                MMA16816(o[2 * vn + 0], ph[kt], &vf[0]);
                MMA16816(o[2 * vn + 0], pl[kt], &vf[0]);
                MMA16816(o[2 * vn + 1], ph[kt], &vf[2]);
                MMA16816(o[2 * vn + 1], pl[kt], &vf[2]);
            }
        }
        __syncthreads();
    }

    float invA = 1.f / lA, invB = 1.f / lB;
    int rloc = wid * 16 + (lane >> 2);
    #pragma unroll
    for (int nt = 0; nt < 16; nt++) {
        int c = nt * 8 + (lane & 3) * 2;
        *(float2*)&Ao[(size_t)rloc * E2_ + c] = make_float2(o[nt][0] * invA, o[nt][1] * invA);
        *(float2*)&Ao[(size_t)(rloc + 8) * E2_ + c] = make_float2(o[nt][2] * invB, o[nt][3] * invB);
    }
}

// ---------------- combine + layernorm + scale: 4 rows/block, float2 ----------
__global__ void __launch_bounds__(256) final_kernel(const float* __restrict__ gamma,
                                                    const float* __restrict__ beta,
                                                    float* __restrict__ Out) {
    int tid = threadIdx.x;
    int row = blockIdx.x * 4 + (tid >> 6);
    int h = row >> 11;
    int t = row & 2047;
    int le = tid & 63;
    int e = le * 2;
    size_t base = ((size_t)h * T_ + t) * E2_;
    float lam = g_lam[h];
    float2 a1 = *(const float2*)&g_att1[base + e];
    float2 a2 = *(const float2*)&g_att2[base + e];
    float v0 = a1.x - lam * a2.x;
    float v1 = a1.y - lam * a2.y;

    float s1 = v0 + v1;
    float s2 = v0 * v0 + v1 * v1;
    #pragma unroll
    for (int off = 16; off; off >>= 1) {
        s1 += __shfl_xor_sync(0xffffffffu, s1, off);
        s2 += __shfl_xor_sync(0xffffffffu, s2, off);
    }
    __shared__ float red[2][8];
    int w = tid >> 5, lane = tid & 31;
    if (lane == 0) { red[0][w] = s1; red[1][w] = s2; }
    __syncthreads();
    int w0 = (tid >> 6) * 2;
    float sum = red[0][w0] + red[0][w0 + 1];
    float sq  = red[1][w0] + red[1][w0 + 1];
    float mu  = sum * (1.f / 128.f);
    float var = fmaxf(sq * (1.f / 128.f) - mu * mu, 0.f);
    float rstd = rsqrtf(var + EPS_);
    float2 g = *(const float2*)&gamma[h * E2_ + e];
    float2 bt = *(const float2*)&beta[h * E2_ + e];
    float2 outv;
    outv.x = ((v0 - mu) * rstd * g.x + bt.x) * OUT_SCALE_;
    outv.y = ((v1 - mu) * rstd * g.y + bt.y) * OUT_SCALE_;
    *(float2*)&Out[base + e] = outv;
}

// ---------------- launch -----------------------------------------------------
extern "C" void kernel_launch(void* const* d_in, const int* in_sizes, int n_in,
                              void* d_out, int out_size) {
    const float* x   = (const float*)d_in[0];
    const float* Wq  = (const float*)d_in[1];
    const float* Wk  = (const float*)d_in[2];
    const float* Wv  = (const float*)d_in[3];
    const float* Wqs = (const float*)d_in[4];
    const float* Wks = (const float*)d_in[5];
    const float* Wvs = (const float*)d_in[6];
    const float* lq1 = (const float*)d_in[7];
    const float* lq2 = (const float*)d_in[8];
    const float* lk1 = (const float*)d_in[9];
    const float* lk2 = (const float*)d_in[10];
    const float* gam = (const float*)d_in[11];
    const float* bet = (const float*)d_in[12];
    float* out = (float*)d_out;

    size_t psmem = 2 * PRJ_STAGEB;   // 110592
    cudaFuncSetAttribute(proj_mma, cudaFuncAttributeMaxDynamicSharedMemorySize, (int)psmem);
    cudaFuncSetAttribute(attn_kernel, cudaFuncAttributeMaxDynamicSharedMemorySize, AT_SMEM);

    lam_kernel<<<1, 32>>>(lq1, lq2, lk1, lk2);
    split_x<<<T_, 256>>>(x);
    transp_w<<<dim3(64, 4, 48), 256>>>(Wq, Wk, Wv);
    proj_mma<<<dim3(16, 16, 3), 256, psmem>>>();
    proj_fix<<<dim3(16, 3, 4), 128>>>(x, Wqs, Wks, Wvs);
    attn_kernel<<<512, 256, AT_SMEM>>>();
    final_kernel<<<8192, 256>>>(gam, bet, out);
}